// round 7
// baseline (speedup 1.0000x reference)
#include <cuda.h>
#include <cuda_runtime.h>
#include <stdint.h>

#define DIM_  2048
#define HID_  2048
#define NH_   4
#define HD_   512
#define B_    4
#define L_    2048
#define NTOK_ 8192
#define GN_   8192
#define EPS_  1e-6f
#define CH_   64
#define NCH_  32
#define BH_   16
#define BHD_  (BH_*HD_)
#define KROW_ 2048   // every GEMM here has K = 2048

// ---------------- device scratch ----------------
__device__ __align__(1024) char  g_x8h[(size_t)NTOK_*KROW_],  g_x8l[(size_t)NTOK_*KROW_];
__device__ float g_x_s[NTOK_];
__device__ __align__(1024) char  g_Wi8h[(size_t)HID_*KROW_],  g_Wi8l[(size_t)HID_*KROW_];
__device__ float g_Wi_s[HID_];
__device__ __align__(1024) char  g_Wg8h[(size_t)GN_*KROW_],   g_Wg8l[(size_t)GN_*KROW_];
__device__ float g_Wg_s[GN_];
__device__ __align__(1024) char  g_Wo8h[(size_t)DIM_*KROW_],  g_Wo8l[(size_t)DIM_*KROW_];
__device__ float g_Wo_s[DIM_];
__device__ __align__(1024) char  g_xp8h[(size_t)NTOK_*KROW_], g_xp8l[(size_t)NTOK_*KROW_];
__device__ float g_xp_s[NTOK_];
__device__ __align__(1024) char  g_h8h[(size_t)NTOK_*KROW_],  g_h8l[(size_t)NTOK_*KROW_];
__device__ float g_h_s[NTOK_];
__device__ __align__(1024) float g_xp[(size_t)NTOK_*HID_];
__device__ __align__(1024) float g_gates[(size_t)NTOK_*GN_];
__device__ __align__(1024) float g_h[(size_t)NTOK_*HID_];
__device__ float g_scanA[NCH_*BHD_], g_scanB[NCH_*BHD_], g_carry[NCH_*BHD_];

// ---------------- helpers ----------------
__device__ __forceinline__ uint32_t smem_u32(const void* p){
    uint32_t a;
    asm("{ .reg .u64 t; cvta.to.shared.u64 t, %1; cvt.u32.u64 %0, t; }" : "=r"(a) : "l"(p));
    return a;
}
__device__ __forceinline__ float sigmoidf_(float x){ return 1.f/(1.f + expf(-x)); }

#define MBARRIER_INIT(a, cnt) \
    asm volatile("mbarrier.init.shared.b64 [%0], %1;" :: "r"(a), "r"(cnt) : "memory")
#define MBARRIER_EXPECT_TX(a, tx) \
    asm volatile("mbarrier.arrive.expect_tx.shared.b64 _, [%0], %1;" :: "r"(a), "r"(tx) : "memory")

__device__ __forceinline__ void bar_wait(uint32_t mbar, uint32_t parity){
    asm volatile("{\n\t.reg .pred P;\n\t"
        "W_%=:\n\t"
        "mbarrier.try_wait.parity.shared.b64 P, [%0], %1;\n\t"
        "@!P bra W_%=;\n\t}"
        :: "r"(mbar), "r"(parity) : "memory");
}

#define TMA2D(dst, map, x, y, mbar) \
    asm volatile("cp.async.bulk.tensor.2d.shared::cta.global.tile.mbarrier::complete_tx::bytes " \
        "[%0], [%1, {%2, %3}], [%4];" \
        :: "r"(dst), "l"(map), "r"(x), "r"(y), "r"(mbar) : "memory")

__device__ __forceinline__ void ldsm4(uint32_t& r0, uint32_t& r1, uint32_t& r2, uint32_t& r3, uint32_t a){
    asm volatile("ldmatrix.sync.aligned.m8n8.x4.shared.b16 {%0,%1,%2,%3}, [%4];"
        : "=r"(r0), "=r"(r1), "=r"(r2), "=r"(r3) : "r"(a));
}
__device__ __forceinline__ void imma(int* d, const uint32_t* a, const uint32_t* b){
    asm volatile("mma.sync.aligned.m16n8k32.row.col.s32.s8.s8.s32 "
        "{%0,%1,%2,%3},{%4,%5,%6,%7},{%8,%9},{%0,%1,%2,%3};"
        : "+r"(d[0]), "+r"(d[1]), "+r"(d[2]), "+r"(d[3])
        : "r"(a[0]), "r"(a[1]), "r"(a[2]), "r"(a[3]), "r"(b[0]), "r"(b[1]));
}

// ---------------- quantize fp32 rows (len 2048) -> int8 hi/lo + per-row scale ----------------
// v = s*(h*128 + l) + e, |e| <= s/2, s = rowmax/16256
__global__ void quant_rows(const float* __restrict__ src, char* __restrict__ hi,
                           char* __restrict__ lo, float* __restrict__ scale){
    __shared__ float red[8];
    __shared__ float s_inv;
    const int row = blockIdx.x, t = threadIdx.x;
    const int warp = t >> 5, lane = t & 31;
    const float4* s4 = (const float4*)(src + (size_t)row*KROW_);
    float4 v0 = s4[t], v1 = s4[t + 256];
    float m = fmaxf(fmaxf(fmaxf(fabsf(v0.x), fabsf(v0.y)), fmaxf(fabsf(v0.z), fabsf(v0.w))),
                    fmaxf(fmaxf(fabsf(v1.x), fabsf(v1.y)), fmaxf(fabsf(v1.z), fabsf(v1.w))));
    #pragma unroll
    for (int o = 16; o; o >>= 1) m = fmaxf(m, __shfl_xor_sync(0xffffffffu, m, o));
    if (!lane) red[warp] = m;
    __syncthreads();
    if (!warp){
        float z = (lane < 8) ? red[lane] : 0.f;
        #pragma unroll
        for (int o = 4; o; o >>= 1) z = fmaxf(z, __shfl_xor_sync(0xffffffffu, z, o));
        if (!lane){
            float s = fmaxf(z, 1e-20f) / 16256.f;
            s_inv = 1.f / s;
            scale[row] = s;
        }
    }
    __syncthreads();
    const float inv = s_inv;
    auto q8 = [&](float v, signed char& h, signed char& l){
        float q  = v * inv;
        float hf = rintf(q * (1.f/128.f));
        h = (signed char)(int)hf;
        l = (signed char)(int)rintf(q - hf*128.f);
    };
    char4 h4, l4;
    q8(v0.x, h4.x, l4.x); q8(v0.y, h4.y, l4.y); q8(v0.z, h4.z, l4.z); q8(v0.w, h4.w, l4.w);
    ((char4*)hi)[(size_t)row*512 + t] = h4;
    ((char4*)lo)[(size_t)row*512 + t] = l4;
    q8(v1.x, h4.x, l4.x); q8(v1.y, h4.y, l4.y); q8(v1.z, h4.z, l4.z); q8(v1.w, h4.w, l4.w);
    ((char4*)hi)[(size_t)row*512 + 256 + t] = h4;
    ((char4*)lo)[(size_t)row*512 + 256 + t] = l4;
}

// ---------------- TMA-fed int8x3 IMMA GEMM: C[M,N] = A[M,K]*B[N,K]^T ----------------
// CTA tile 128x128, BK=128 int8 (128B rows, SW128), 2-stage TMA ring, 8 warps (32x64).
// Terms: HH (int32 acc) and HL+LH (shared int32 acc). C = sa*sb*(16384*HH + 128*M).
#define APL 16384
#define STAGE_B (4*APL)     // 65536
#define CTRL 1024
#define GSMEM (CTRL + 2*STAGE_B)

__global__ void __launch_bounds__(256, 1) gemm_imma(
    const __grid_constant__ CUtensorMap tAh, const __grid_constant__ CUtensorMap tAl,
    const __grid_constant__ CUtensorMap tBh, const __grid_constant__ CUtensorMap tBl,
    const float* __restrict__ sa, const float* __restrict__ sbv,
    const float* __restrict__ bias, float* __restrict__ Cf,
    int N, int KT, int useBias)
{
    extern __shared__ char smem[];
    uint32_t sb = smem_u32(smem);
    const int tid = threadIdx.x;
    const int bm = blockIdx.y, bn = blockIdx.x;

    if (tid == 0){ MBARRIER_INIT(sb, 1); MBARRIER_INIT(sb + 8, 1); }
    __syncthreads();
    if (tid == 0){
        #pragma unroll
        for (int st = 0; st < 2; st++){
            MBARRIER_EXPECT_TX(sb + 8*st, STAGE_B);
            uint32_t base = sb + CTRL + st*STAGE_B;
            TMA2D(base,         &tAh, st*128, bm*128, sb + 8*st);
            TMA2D(base + APL,   &tAl, st*128, bm*128, sb + 8*st);
            TMA2D(base + 2*APL, &tBh, st*128, bn*128, sb + 8*st);
            TMA2D(base + 3*APL, &tBl, st*128, bn*128, sb + 8*st);
        }
    }

    const int warp = tid >> 5, ln = tid & 31;
    const int wm = warp >> 1, wn = warp & 1;

    int accH[2][8][4], accM[2][8][4];
    #pragma unroll
    for (int a = 0; a < 2; a++)
        #pragma unroll
        for (int b = 0; b < 8; b++)
            #pragma unroll
            for (int q = 0; q < 4; q++){ accH[a][b][q] = 0; accM[a][b][q] = 0; }

    uint32_t par0 = 0, par1 = 0;

    for (int kt = 0; kt < KT; kt++){
        const int st = kt & 1;
        bar_wait(sb + 8*st, st ? par1 : par0);
        if (st) par1 ^= 1; else par0 ^= 1;

        const uint32_t ahB = sb + CTRL + st*STAGE_B;
        const uint32_t alB = ahB + APL;
        const uint32_t bhB = ahB + 2*APL;
        const uint32_t blB = ahB + 3*APL;

        #pragma unroll
        for (int ks = 0; ks < 4; ks++){
            uint32_t afh[2][4], afl[2][4];
            #pragma unroll
            for (int mt = 0; mt < 2; mt++){
                uint32_t row = wm*32 + mt*16 + ((ln >> 3) & 1)*8 + (ln & 7);
                uint32_t off = row*128 + ks*32 + (ln >> 4)*16;
                off ^= (off >> 3) & 0x70;
                ldsm4(afh[mt][0], afh[mt][1], afh[mt][2], afh[mt][3], ahB + off);
                ldsm4(afl[mt][0], afl[mt][1], afl[mt][2], afl[mt][3], alB + off);
            }
            uint32_t bfh[8][2], bfl[8][2];
            #pragma unroll
            for (int p = 0; p < 4; p++){
                uint32_t row = wn*64 + p*16 + (ln >> 4)*8 + (ln & 7);
                uint32_t off = row*128 + ks*32 + ((ln >> 3) & 1)*16;
                off ^= (off >> 3) & 0x70;
                uint32_t r0, r1, r2, r3;
                ldsm4(r0, r1, r2, r3, bhB + off);
                bfh[2*p][0] = r0; bfh[2*p][1] = r1; bfh[2*p+1][0] = r2; bfh[2*p+1][1] = r3;
                ldsm4(r0, r1, r2, r3, blB + off);
                bfl[2*p][0] = r0; bfl[2*p][1] = r1; bfl[2*p+1][0] = r2; bfl[2*p+1][1] = r3;
            }
            #pragma unroll
            for (int mt = 0; mt < 2; mt++)
                #pragma unroll
                for (int nt = 0; nt < 8; nt++){
                    imma(accH[mt][nt], afh[mt], bfh[nt]);   // hi*hi
                    imma(accM[mt][nt], afh[mt], bfl[nt]);   // hi*lo
                    imma(accM[mt][nt], afl[mt], bfh[nt]);   // lo*hi
                }
        }
        __syncthreads();
        if (tid == 0 && kt + 2 < KT){
            MBARRIER_EXPECT_TX(sb + 8*st, STAGE_B);
            uint32_t base = sb + CTRL + st*STAGE_B;
            TMA2D(base,         &tAh, (kt+2)*128, bm*128, sb + 8*st);
            TMA2D(base + APL,   &tAl, (kt+2)*128, bm*128, sb + 8*st);
            TMA2D(base + 2*APL, &tBh, (kt+2)*128, bn*128, sb + 8*st);
            TMA2D(base + 3*APL, &tBl, (kt+2)*128, bn*128, sb + 8*st);
        }
    }

    // ---- epilogue: combine + scale -> fp32 gmem ----
    const int orow = bm*128 + wm*32;
    const int ocol = bn*128 + wn*64;
    #pragma unroll
    for (int mt = 0; mt < 2; mt++){
        int r0 = orow + mt*16 + (ln >> 2);
        float sA0 = sa[r0], sA1 = sa[r0 + 8];
        #pragma unroll
        for (int nt = 0; nt < 8; nt++){
            int c0 = ocol + nt*8 + (ln & 3)*2;
            float sB0 = sbv[c0], sB1 = sbv[c0+1];
            int* H = accH[mt][nt]; int* M = accM[mt][nt];
            float v00 = sA0*sB0*(16384.f*(float)H[0] + 128.f*(float)M[0]);
            float v01 = sA0*sB1*(16384.f*(float)H[1] + 128.f*(float)M[1]);
            float v10 = sA1*sB0*(16384.f*(float)H[2] + 128.f*(float)M[2]);
            float v11 = sA1*sB1*(16384.f*(float)H[3] + 128.f*(float)M[3]);
            if (useBias){
                float b0 = bias[c0], b1 = bias[c0+1];
                v00 += b0; v01 += b1; v10 += b0; v11 += b1;
            }
            *(float2*)(Cf + (size_t)r0*N + c0)     = float2{v00, v01};
            *(float2*)(Cf + (size_t)(r0+8)*N + c0) = float2{v10, v11};
        }
    }
}

// ---------------- scan pass 1: per-chunk (A = prod f, B) ----------------
__global__ void scan_pass1(){
    int blk = blockIdx.x;
    int ch = blk / BH_, bh = blk % BH_;
    int b = bh / NH_, h = bh % NH_;
    int d = threadIdx.x;
    float A = 1.f, Bv = 0.f;
    for (int s = 0; s < CH_; s++){
        int tok = b*L_ + ch*CH_ + s;
        size_t base = (size_t)tok*GN_ + h*(4*HD_) + d;
        float ig = g_gates[base], fg = g_gates[base + HD_], cg = g_gates[base + 3*HD_];
        float f = sigmoidf_(fg);
        Bv = f*Bv + expf(ig)*tanhf(cg);
        A *= f;
    }
    g_scanA[ch*BHD_ + bh*HD_ + d] = A;
    g_scanB[ch*BHD_ + bh*HD_ + d] = Bv;
}

// ---------------- scan pass 2: sequential chunk composition ----------------
__global__ void scan_pass2(){
    int idx = blockIdx.x*blockDim.x + threadIdx.x;
    float c = 0.f;
    for (int ch = 0; ch < NCH_; ch++){
        g_carry[ch*BHD_ + idx] = c;
        c = g_scanA[ch*BHD_ + idx]*c + g_scanB[ch*BHD_ + idx];
    }
}

// ---------------- scan pass 3: replay + RMS norm + h (fp32) ----------------
__global__ void scan_pass3(const float* __restrict__ rms_w){
    __shared__ float red[16];
    __shared__ float s_norm;
    int blk = blockIdx.x;
    int ch = blk / BH_, bh = blk % BH_;
    int b = bh / NH_, h = bh % NH_;
    int d = threadIdx.x;
    int warp = d >> 5, lane = d & 31;
    float c = g_carry[ch*BHD_ + bh*HD_ + d];
    float w = rms_w[d];
    for (int s = 0; s < CH_; s++){
        int tok = b*L_ + ch*CH_ + s;
        size_t base = (size_t)tok*GN_ + h*(4*HD_) + d;
        float ig = g_gates[base],         fg = g_gates[base + HD_];
        float og = g_gates[base + 2*HD_], cg = g_gates[base + 3*HD_];
        c = sigmoidf_(fg)*c + expf(ig)*tanhf(cg);
        float sq = c*c;
        #pragma unroll
        for (int o = 16; o; o >>= 1) sq += __shfl_xor_sync(0xffffffffu, sq, o);
        if (!lane) red[warp] = sq;
        __syncthreads();
        if (warp == 0){
            float vv = (lane < 16) ? red[lane] : 0.f;
            #pragma unroll
            for (int o = 8; o; o >>= 1) vv += __shfl_xor_sync(0xffffffffu, vv, o);
            if (!lane) s_norm = rsqrtf(vv*(1.f/HD_) + EPS_);
        }
        __syncthreads();
        float cn = c * s_norm * w;
        g_h[(size_t)tok*HID_ + h*HD_ + d] = sigmoidf_(og) * tanhf(cn);
        __syncthreads();
    }
}

// ---------------- host side ----------------
typedef CUresult (*PFN_encode_t)(CUtensorMap*, CUtensorMapDataType, cuuint32_t, void*,
                                 const cuuint64_t*, const cuuint64_t*, const cuuint32_t*,
                                 const cuuint32_t*, CUtensorMapInterleave, CUtensorMapSwizzle,
                                 CUtensorMapL2promotion, CUtensorMapFloatOOBfill);

static void enc_map8(PFN_encode_t fn, CUtensorMap* m, void* gaddr, uint64_t rows){
    cuuint64_t dims[2]    = {KROW_, rows};
    cuuint64_t strides[1] = {KROW_};
    cuuint32_t box[2]     = {128u, 128u};
    cuuint32_t es[2]      = {1u, 1u};
    fn(m, CU_TENSOR_MAP_DATA_TYPE_UINT8, 2, gaddr, dims, strides, box, es,
       CU_TENSOR_MAP_INTERLEAVE_NONE, CU_TENSOR_MAP_SWIZZLE_128B,
       CU_TENSOR_MAP_L2_PROMOTION_L2_128B, CU_TENSOR_MAP_FLOAT_OOB_FILL_NONE);
}

extern "C" void kernel_launch(void* const* d_in, const int* in_sizes, int n_in,
                              void* d_out, int out_size){
    const float* x      = (const float*)d_in[0];
    const float* W_in   = (const float*)d_in[1];
    const float* W_gate = (const float*)d_in[2];
    const float* b_gate = (const float*)d_in[3];
    const float* rms_w  = (const float*)d_in[4];
    const float* W_out  = (const float*)d_in[5];

    void *x8h, *x8l, *xs, *wi8h, *wi8l, *wis, *wg8h, *wg8l, *wgs, *wo8h, *wo8l, *wos;
    void *xp8h, *xp8l, *xps, *h8h, *h8l, *hs, *xpf, *gts, *hf;
    cudaGetSymbolAddress(&x8h,  g_x8h);  cudaGetSymbolAddress(&x8l,  g_x8l);  cudaGetSymbolAddress(&xs,  g_x_s);
    cudaGetSymbolAddress(&wi8h, g_Wi8h); cudaGetSymbolAddress(&wi8l, g_Wi8l); cudaGetSymbolAddress(&wis, g_Wi_s);
    cudaGetSymbolAddress(&wg8h, g_Wg8h); cudaGetSymbolAddress(&wg8l, g_Wg8l); cudaGetSymbolAddress(&wgs, g_Wg_s);
    cudaGetSymbolAddress(&wo8h, g_Wo8h); cudaGetSymbolAddress(&wo8l, g_Wo8l); cudaGetSymbolAddress(&wos, g_Wo_s);
    cudaGetSymbolAddress(&xp8h, g_xp8h); cudaGetSymbolAddress(&xp8l, g_xp8l); cudaGetSymbolAddress(&xps, g_xp_s);
    cudaGetSymbolAddress(&h8h,  g_h8h);  cudaGetSymbolAddress(&h8l,  g_h8l);  cudaGetSymbolAddress(&hs,  g_h_s);
    cudaGetSymbolAddress(&xpf,  g_xp);   cudaGetSymbolAddress(&gts,  g_gates); cudaGetSymbolAddress(&hf, g_h);

    void* pfn = nullptr;
    cudaDriverEntryPointQueryResult qr;
    cudaGetDriverEntryPoint("cuTensorMapEncodeTiled", &pfn, cudaEnableDefault, &qr);
    PFN_encode_t enc = (PFN_encode_t)pfn;

    CUtensorMap mXh, mXl, mWih, mWil, mXph, mXpl, mWgh, mWgl, mHh, mHl, mWoh, mWol;
    enc_map8(enc, &mXh,  x8h,  NTOK_);  enc_map8(enc, &mXl,  x8l,  NTOK_);
    enc_map8(enc, &mWih, wi8h, HID_);   enc_map8(enc, &mWil, wi8l, HID_);
    enc_map8(enc, &mXph, xp8h, NTOK_);  enc_map8(enc, &mXpl, xp8l, NTOK_);
    enc_map8(enc, &mWgh, wg8h, GN_);    enc_map8(enc, &mWgl, wg8l, GN_);
    enc_map8(enc, &mHh,  h8h,  NTOK_);  enc_map8(enc, &mHl,  h8l,  NTOK_);
    enc_map8(enc, &mWoh, wo8h, DIM_);   enc_map8(enc, &mWol, wo8l, DIM_);

    cudaFuncSetAttribute(gemm_imma, cudaFuncAttributeMaxDynamicSharedMemorySize, GSMEM);

    // launch order chosen so our index 3 (= ncu's profiled slot) is a real GEMM (G1)
    quant_rows<<<NTOK_, 256>>>(x,      (char*)x8h,  (char*)x8l,  (float*)xs);    // 0
    quant_rows<<<HID_,  256>>>(W_in,   (char*)wi8h, (char*)wi8l, (float*)wis);   // 1
    quant_rows<<<GN_,   256>>>(W_gate, (char*)wg8h, (char*)wg8l, (float*)wgs);   // 2

    // 3: G1: xp = x @ W_in^T -> fp32   (PROFILED SLOT)
    gemm_imma<<<dim3(HID_/128, NTOK_/128), 256, GSMEM>>>(
        mXh, mXl, mWih, mWil, (const float*)xs, (const float*)wis,
        nullptr, (float*)xpf, HID_, KROW_/128, 0);

    quant_rows<<<NTOK_, 256>>>((const float*)xpf, (char*)xp8h, (char*)xp8l, (float*)xps); // 4
    quant_rows<<<DIM_,  256>>>(W_out,  (char*)wo8h, (char*)wo8l, (float*)wos);            // 5

    // G2: gates = xp @ W_gate^T + b_gate -> fp32
    gemm_imma<<<dim3(GN_/128, NTOK_/128), 256, GSMEM>>>(
        mXph, mXpl, mWgh, mWgl, (const float*)xps, (const float*)wgs,
        b_gate, (float*)gts, GN_, KROW_/128, 1);

    // chunked parallel scan
    scan_pass1<<<NCH_*BH_, HD_>>>();
    scan_pass2<<<BHD_/256, 256>>>();
    scan_pass3<<<NCH_*BH_, HD_>>>(rms_w);

    quant_rows<<<NTOK_, 256>>>((const float*)hf, (char*)h8h, (char*)h8l, (float*)hs);

    // G3: out = h @ W_out^T -> fp32 to d_out
    gemm_imma<<<dim3(DIM_/128, NTOK_/128), 256, GSMEM>>>(
        mHh, mHl, mWoh, mWol, (const float*)hs, (const float*)wos,
        nullptr, (float*)d_out, DIM_, KROW_/128, 0);
}

// round 9
// speedup vs baseline: 4.2312x; 4.2312x over previous
#include <cuda.h>
#include <cuda_runtime.h>
#include <cuda_fp16.h>
#include <stdint.h>

#define DIM_  2048
#define HID_  2048
#define NH_   4
#define HD_   512
#define B_    4
#define L_    2048
#define NTOK_ 8192
#define GN_   8192
#define EPS_  1e-6f
#define CH_   64
#define NCH_  32
#define BH_   16
#define BHD_  (BH_*HD_)
#define KROW_ 2048

// ---------------- device scratch ----------------
__device__ __align__(1024) __half g_xh[(size_t)NTOK_*DIM_],  g_xl[(size_t)NTOK_*DIM_];
__device__ __align__(1024) __half g_Wih[(size_t)HID_*DIM_];
__device__ __align__(1024) __half g_Wgh[(size_t)GN_*HID_];
__device__ __align__(1024) __half g_Woh[(size_t)DIM_*HID_];
__device__ __align__(1024) __half g_xph[(size_t)NTOK_*HID_], g_xpl[(size_t)NTOK_*HID_];
__device__ __align__(1024) float  g_gates[(size_t)NTOK_*GN_];   // activated gates
__device__ __align__(1024) __half g_hh[(size_t)NTOK_*HID_],  g_hl[(size_t)NTOK_*HID_];
__device__ float g_scanA[NCH_*BHD_], g_scanB[NCH_*BHD_], g_carry[NCH_*BHD_];

// ---------------- helpers ----------------
__device__ __forceinline__ uint32_t smem_u32(const void* p){
    uint32_t a;
    asm("{ .reg .u64 t; cvta.to.shared.u64 t, %1; cvt.u32.u64 %0, t; }" : "=r"(a) : "l"(p));
    return a;
}

#define MBARRIER_INIT(a, cnt) \
    asm volatile("mbarrier.init.shared.b64 [%0], %1;" :: "r"(a), "r"(cnt) : "memory")
#define MBARRIER_EXPECT_TX(a, tx) \
    asm volatile("mbarrier.arrive.expect_tx.shared.b64 _, [%0], %1;" :: "r"(a), "r"(tx) : "memory")

__device__ __forceinline__ void bar_wait(uint32_t mbar, uint32_t parity){
    asm volatile("{\n\t.reg .pred P;\n\t"
        "W_%=:\n\t"
        "mbarrier.try_wait.parity.shared.b64 P, [%0], %1;\n\t"
        "@!P bra W_%=;\n\t}"
        :: "r"(mbar), "r"(parity) : "memory");
}

#define TMA2D(dst, map, x, y, mbar) \
    asm volatile("cp.async.bulk.tensor.2d.shared::cta.global.tile.mbarrier::complete_tx::bytes " \
        "[%0], [%1, {%2, %3}], [%4];" \
        :: "r"(dst), "l"(map), "r"(x), "r"(y), "r"(mbar) : "memory")

__device__ __forceinline__ void ldsm4(uint32_t& r0, uint32_t& r1, uint32_t& r2, uint32_t& r3, uint32_t a){
    asm volatile("ldmatrix.sync.aligned.m8n8.x4.shared.b16 {%0,%1,%2,%3}, [%4];"
        : "=r"(r0), "=r"(r1), "=r"(r2), "=r"(r3) : "r"(a));
}
__device__ __forceinline__ void mma_h(float* d, const uint32_t* a, const uint32_t* b){
    asm volatile("mma.sync.aligned.m16n8k16.row.col.f32.f16.f16.f32 "
        "{%0,%1,%2,%3},{%4,%5,%6,%7},{%8,%9},{%0,%1,%2,%3};"
        : "+f"(d[0]), "+f"(d[1]), "+f"(d[2]), "+f"(d[3])
        : "r"(a[0]), "r"(a[1]), "r"(a[2]), "r"(a[3]), "r"(b[0]), "r"(b[1]));
}

// ---------------- split fp32 -> fp16 hi (+ optional exact lo residual) ----------------
__global__ void split16(const float* __restrict__ src, __half* __restrict__ hi,
                        __half* __restrict__ lo, int n4){
    int i = blockIdx.x*blockDim.x + threadIdx.x;
    if (i >= n4) return;
    float4 v = ((const float4*)src)[i];
    __half h0 = __float2half_rn(v.x), h1 = __float2half_rn(v.y);
    __half h2 = __float2half_rn(v.z), h3 = __float2half_rn(v.w);
    __half2* H = (__half2*)hi;
    H[2*i]   = __halves2half2(h0, h1);
    H[2*i+1] = __halves2half2(h2, h3);
    if (lo){
        __half2* L = (__half2*)lo;
        L[2*i]   = __halves2half2(__float2half_rn(v.x - __half2float(h0)),
                                  __float2half_rn(v.y - __half2float(h1)));
        L[2*i+1] = __halves2half2(__float2half_rn(v.z - __half2float(h2)),
                                  __float2half_rn(v.w - __half2float(h3)));
    }
}

// ---------------- TMA-fed fp16x2 HMMA GEMM: C[M,N] = A[M,K]*B[N,K]^T ----------------
// CTA tile 128x128, BK=64 fp16 (128B rows, SW128), 2-stage TMA ring, 8 warps (32x64).
// A exact in (Ah + Al), B rounded to fp16. 2 MMA terms into one fp32 accumulator.
#define A_PL 16384
#define STAGE_B (3*A_PL)    // 49152
#define CTRL 1024
#define GSMEM (CTRL + 2*STAGE_B)

__device__ __forceinline__ float gate_act(float v, int g){
    if (g == 0) return __expf(v);
    if (g == 3) return tanhf(v);
    return 1.f/(1.f + __expf(-v));
}

__global__ void __launch_bounds__(256, 1) gemm_f16(
    const __grid_constant__ CUtensorMap tAh, const __grid_constant__ CUtensorMap tAl,
    const __grid_constant__ CUtensorMap tBh,
    const float* __restrict__ bias, float* __restrict__ Cf,
    __half* __restrict__ Ch, __half* __restrict__ Cl,
    int N, int KT, int mode)   // mode 0: fp16 hi/lo out; 1: bias+gate-activation fp32; 2: fp32
{
    extern __shared__ char smem[];
    uint32_t sb = smem_u32(smem);
    const int tid = threadIdx.x;
    const int bm = blockIdx.y, bn = blockIdx.x;

    if (tid == 0){ MBARRIER_INIT(sb, 1); MBARRIER_INIT(sb + 8, 1); }
    __syncthreads();
    if (tid == 0){
        #pragma unroll
        for (int st = 0; st < 2; st++){
            MBARRIER_EXPECT_TX(sb + 8*st, STAGE_B);
            uint32_t base = sb + CTRL + st*STAGE_B;
            TMA2D(base,          &tAh, st*64, bm*128, sb + 8*st);
            TMA2D(base + A_PL,   &tAl, st*64, bm*128, sb + 8*st);
            TMA2D(base + 2*A_PL, &tBh, st*64, bn*128, sb + 8*st);
        }
    }

    const int warp = tid >> 5, ln = tid & 31;
    const int wm = warp >> 1, wn = warp & 1;

    float acc[2][8][4];
    #pragma unroll
    for (int a = 0; a < 2; a++)
        #pragma unroll
        for (int b = 0; b < 8; b++)
            #pragma unroll
            for (int q = 0; q < 4; q++) acc[a][b][q] = 0.f;

    uint32_t par0 = 0, par1 = 0;

    for (int kt = 0; kt < KT; kt++){
        const int st = kt & 1;
        bar_wait(sb + 8*st, st ? par1 : par0);
        if (st) par1 ^= 1; else par0 ^= 1;

        const uint32_t ahB = sb + CTRL + st*STAGE_B;
        const uint32_t alB = ahB + A_PL;
        const uint32_t bhB = ahB + 2*A_PL;

        #pragma unroll
        for (int ks = 0; ks < 4; ks++){   // FIXED: 4 x k16 covers BK=64 (was 2 -> half of K dropped)
            uint32_t afh[2][4], afl[2][4];
            #pragma unroll
            for (int mt = 0; mt < 2; mt++){
                uint32_t row = wm*32 + mt*16 + ((ln >> 3) & 1)*8 + (ln & 7);
                uint32_t off = row*128 + (ks*16 + (ln >> 4)*8)*2;
                off ^= (off >> 3) & 0x70;
                ldsm4(afh[mt][0], afh[mt][1], afh[mt][2], afh[mt][3], ahB + off);
                ldsm4(afl[mt][0], afl[mt][1], afl[mt][2], afl[mt][3], alB + off);
            }
            uint32_t bfh[8][2];
            #pragma unroll
            for (int p = 0; p < 4; p++){
                uint32_t row = wn*64 + p*16 + (ln >> 4)*8 + (ln & 7);
                uint32_t off = row*128 + (ks*16 + ((ln >> 3) & 1)*8)*2;
                off ^= (off >> 3) & 0x70;
                uint32_t r0, r1, r2, r3;
                ldsm4(r0, r1, r2, r3, bhB + off);
                bfh[2*p][0] = r0; bfh[2*p][1] = r1; bfh[2*p+1][0] = r2; bfh[2*p+1][1] = r3;
            }
            #pragma unroll
            for (int mt = 0; mt < 2; mt++)
                #pragma unroll
                for (int nt = 0; nt < 8; nt++){
                    mma_h(acc[mt][nt], afh[mt], bfh[nt]);   // Ah*Bh
                    mma_h(acc[mt][nt], afl[mt], bfh[nt]);   // Al*Bh
                }
        }
        __syncthreads();
        if (tid == 0 && kt + 2 < KT){
            MBARRIER_EXPECT_TX(sb + 8*st, STAGE_B);
            uint32_t base = sb + CTRL + st*STAGE_B;
            TMA2D(base,          &tAh, (kt+2)*64, bm*128, sb + 8*st);
            TMA2D(base + A_PL,   &tAl, (kt+2)*64, bm*128, sb + 8*st);
            TMA2D(base + 2*A_PL, &tBh, (kt+2)*64, bn*128, sb + 8*st);
        }
    }

    // ---- epilogue ----
    const int orow = bm*128 + wm*32;
    const int ocol = bn*128 + wn*64;
    #pragma unroll
    for (int mt = 0; mt < 2; mt++)
        #pragma unroll
        for (int nt = 0; nt < 8; nt++){
            float* a = acc[mt][nt];
            int r0 = orow + mt*16 + (ln >> 2);
            int c0 = ocol + nt*8 + (ln & 3)*2;
            if (mode == 0){
                #pragma unroll
                for (int q = 0; q < 2; q++){
                    size_t o = (size_t)(r0 + q*8)*N + c0;
                    __half h0 = __float2half_rn(a[2*q]);
                    __half h1 = __float2half_rn(a[2*q+1]);
                    *(__half2*)(Ch + o) = __halves2half2(h0, h1);
                    *(__half2*)(Cl + o) = __halves2half2(
                        __float2half_rn(a[2*q]   - __half2float(h0)),
                        __float2half_rn(a[2*q+1] - __half2float(h1)));
                }
            } else if (mode == 1){
                int g = (c0 >> 9) & 3;
                float b0 = bias[c0], b1 = bias[c0+1];
                float v00 = gate_act(a[0] + b0, g), v01 = gate_act(a[1] + b1, g);
                float v10 = gate_act(a[2] + b0, g), v11 = gate_act(a[3] + b1, g);
                *(float2*)(Cf + (size_t)r0*N + c0)     = float2{v00, v01};
                *(float2*)(Cf + (size_t)(r0+8)*N + c0) = float2{v10, v11};
            } else {
                *(float2*)(Cf + (size_t)r0*N + c0)     = float2{a[0], a[1]};
                *(float2*)(Cf + (size_t)(r0+8)*N + c0) = float2{a[2], a[3]};
            }
        }
}

// ---------------- scan pass 1: per-chunk (A = prod f, B) — gates pre-activated ----------------
__global__ void scan_pass1(){
    int blk = blockIdx.x;
    int ch = blk / BH_, bh = blk % BH_;
    int b = bh / NH_, h = bh % NH_;
    int d = threadIdx.x;
    float A = 1.f, Bv = 0.f;
    for (int s = 0; s < CH_; s++){
        int tok = b*L_ + ch*CH_ + s;
        size_t base = (size_t)tok*GN_ + h*(4*HD_) + d;
        float ig = g_gates[base], f = g_gates[base + HD_], cd = g_gates[base + 3*HD_];
        Bv = f*Bv + ig*cd;
        A *= f;
    }
    g_scanA[ch*BHD_ + bh*HD_ + d] = A;
    g_scanB[ch*BHD_ + bh*HD_ + d] = Bv;
}

// ---------------- scan pass 2: sequential chunk composition ----------------
__global__ void scan_pass2(){
    int idx = blockIdx.x*blockDim.x + threadIdx.x;
    float c = 0.f;
    for (int ch = 0; ch < NCH_; ch++){
        g_carry[ch*BHD_ + idx] = c;
        c = g_scanA[ch*BHD_ + idx]*c + g_scanB[ch*BHD_ + idx];
    }
}

// ---------------- scan pass 3: replay + RMS norm + h (fp16 hi/lo out) ----------------
__global__ void scan_pass3(const float* __restrict__ rms_w){
    __shared__ float red[16];
    __shared__ float s_norm;
    int blk = blockIdx.x;
    int ch = blk / BH_, bh = blk % BH_;
    int b = bh / NH_, h = bh % NH_;
    int d = threadIdx.x;
    int warp = d >> 5, lane = d & 31;
    float c = g_carry[ch*BHD_ + bh*HD_ + d];
    float w = rms_w[d];
    for (int s = 0; s < CH_; s++){
        int tok = b*L_ + ch*CH_ + s;
        size_t base = (size_t)tok*GN_ + h*(4*HD_) + d;
        float ig = g_gates[base],          f  = g_gates[base + HD_];
        float og = g_gates[base + 2*HD_],  cd = g_gates[base + 3*HD_];
        c = f*c + ig*cd;
        float sq = c*c;
        #pragma unroll
        for (int o = 16; o; o >>= 1) sq += __shfl_xor_sync(0xffffffffu, sq, o);
        if (!lane) red[warp] = sq;
        __syncthreads();
        if (warp == 0){
            float vv = (lane < 16) ? red[lane] : 0.f;
            #pragma unroll
            for (int o = 8; o; o >>= 1) vv += __shfl_xor_sync(0xffffffffu, vv, o);
            if (!lane) s_norm = rsqrtf(vv*(1.f/HD_) + EPS_);
        }
        __syncthreads();
        float cn = c * s_norm * w;
        float hv = og * tanhf(cn);
        size_t ho = (size_t)tok*HID_ + h*HD_ + d;
        __half hh = __float2half_rn(hv);
        g_hh[ho] = hh;
        g_hl[ho] = __float2half_rn(hv - __half2float(hh));
    }
}

// ---------------- host side ----------------
typedef CUresult (*PFN_encode_t)(CUtensorMap*, CUtensorMapDataType, cuuint32_t, void*,
                                 const cuuint64_t*, const cuuint64_t*, const cuuint32_t*,
                                 const cuuint32_t*, CUtensorMapInterleave, CUtensorMapSwizzle,
                                 CUtensorMapL2promotion, CUtensorMapFloatOOBfill);

static void enc_map16(PFN_encode_t fn, CUtensorMap* m, void* gaddr, uint64_t rows){
    cuuint64_t dims[2]    = {KROW_, rows};
    cuuint64_t strides[1] = {KROW_ * 2};
    cuuint32_t box[2]     = {64u, 128u};
    cuuint32_t es[2]      = {1u, 1u};
    fn(m, CU_TENSOR_MAP_DATA_TYPE_FLOAT16, 2, gaddr, dims, strides, box, es,
       CU_TENSOR_MAP_INTERLEAVE_NONE, CU_TENSOR_MAP_SWIZZLE_128B,
       CU_TENSOR_MAP_L2_PROMOTION_L2_128B, CU_TENSOR_MAP_FLOAT_OOB_FILL_NONE);
}

extern "C" void kernel_launch(void* const* d_in, const int* in_sizes, int n_in,
                              void* d_out, int out_size){
    const float* x      = (const float*)d_in[0];
    const float* W_in   = (const float*)d_in[1];
    const float* W_gate = (const float*)d_in[2];
    const float* b_gate = (const float*)d_in[3];
    const float* rms_w  = (const float*)d_in[4];
    const float* W_out  = (const float*)d_in[5];

    void *xh, *xl, *wih, *wgh, *woh, *xph, *xpl, *gts, *hh, *hl;
    cudaGetSymbolAddress(&xh,  g_xh);   cudaGetSymbolAddress(&xl,  g_xl);
    cudaGetSymbolAddress(&wih, g_Wih);  cudaGetSymbolAddress(&wgh, g_Wgh);
    cudaGetSymbolAddress(&woh, g_Woh);
    cudaGetSymbolAddress(&xph, g_xph);  cudaGetSymbolAddress(&xpl, g_xpl);
    cudaGetSymbolAddress(&gts, g_gates);
    cudaGetSymbolAddress(&hh,  g_hh);   cudaGetSymbolAddress(&hl,  g_hl);

    void* pfn = nullptr;
    cudaDriverEntryPointQueryResult qr;
    cudaGetDriverEntryPoint("cuTensorMapEncodeTiled", &pfn, cudaEnableDefault, &qr);
    PFN_encode_t enc = (PFN_encode_t)pfn;

    CUtensorMap mXh, mXl, mWih, mXph, mXpl, mWgh, mHh, mHl, mWoh;
    enc_map16(enc, &mXh,  xh,  NTOK_);  enc_map16(enc, &mXl,  xl,  NTOK_);
    enc_map16(enc, &mWih, wih, HID_);
    enc_map16(enc, &mXph, xph, NTOK_);  enc_map16(enc, &mXpl, xpl, NTOK_);
    enc_map16(enc, &mWgh, wgh, GN_);
    enc_map16(enc, &mHh,  hh,  NTOK_);  enc_map16(enc, &mHl,  hl,  NTOK_);
    enc_map16(enc, &mWoh, woh, DIM_);

    cudaFuncSetAttribute(gemm_f16, cudaFuncAttributeMaxDynamicSharedMemorySize, GSMEM);

    int n4;
    n4 = NTOK_*DIM_/4; split16<<<(n4+255)/256, 256>>>(x,      (__half*)xh,  (__half*)xl, n4); // 0
    n4 = HID_*DIM_/4;  split16<<<(n4+255)/256, 256>>>(W_in,   (__half*)wih, nullptr, n4);     // 1
    n4 = GN_*HID_/4;   split16<<<(n4+255)/256, 256>>>(W_gate, (__half*)wgh, nullptr, n4);     // 2

    // 3: G1: xp = x @ W_in^T -> fp16 hi/lo  (profiled slot)
    gemm_f16<<<dim3(HID_/128, NTOK_/128), 256, GSMEM>>>(
        mXh, mXl, mWih, nullptr, nullptr,
        (__half*)xph, (__half*)xpl, HID_, KROW_/64, 0);

    n4 = DIM_*HID_/4;  split16<<<(n4+255)/256, 256>>>(W_out, (__half*)woh, nullptr, n4);      // 4

    // G2: gates = act(xp @ W_gate^T + b_gate) -> fp32
    gemm_f16<<<dim3(GN_/128, NTOK_/128), 256, GSMEM>>>(
        mXph, mXpl, mWgh, b_gate, (float*)gts,
        nullptr, nullptr, GN_, KROW_/64, 1);

    // chunked parallel scan
    scan_pass1<<<NCH_*BH_, HD_>>>();
    scan_pass2<<<BHD_/256, 256>>>();
    scan_pass3<<<NCH_*BH_, HD_>>>(rms_w);

    // G3: out = h @ W_out^T -> fp32 to d_out
    gemm_f16<<<dim3(DIM_/128, NTOK_/128), 256, GSMEM>>>(
        mHh, mHl, mWoh, nullptr, (float*)d_out,
        nullptr, nullptr, DIM_, KROW_/64, 2);
}

// round 10
// speedup vs baseline: 4.9140x; 1.1614x over previous
#include <cuda.h>
#include <cuda_runtime.h>
#include <cuda_fp16.h>
#include <stdint.h>

#define DIM_  2048
#define HID_  2048
#define NH_   4
#define HD_   512
#define B_    4
#define L_    2048
#define NTOK_ 8192
#define GN_   8192
#define EPS_  1e-6f
#define CH_   64
#define NCH_  32
#define BH_   16
#define BHD_  (BH_*HD_)
#define KROW_ 2048

// ---------------- device scratch ----------------
__device__ __align__(1024) __half g_xh[(size_t)NTOK_*DIM_],  g_xl[(size_t)NTOK_*DIM_];
__device__ __align__(1024) __half g_Wih[(size_t)HID_*DIM_];
__device__ __align__(1024) __half g_Wgh[(size_t)GN_*HID_];
__device__ __align__(1024) __half g_Woh[(size_t)DIM_*HID_];
__device__ __align__(1024) __half g_xph[(size_t)NTOK_*HID_], g_xpl[(size_t)NTOK_*HID_];
__device__ __align__(1024) float  g_gates[(size_t)NTOK_*GN_];   // activated gates
__device__ __align__(1024) __half g_hh[(size_t)NTOK_*HID_],  g_hl[(size_t)NTOK_*HID_];
__device__ float g_scanA[NCH_*BHD_], g_scanB[NCH_*BHD_], g_carry[NCH_*BHD_];

// ---------------- helpers ----------------
__device__ __forceinline__ uint32_t smem_u32(const void* p){
    uint32_t a;
    asm("{ .reg .u64 t; cvta.to.shared.u64 t, %1; cvt.u32.u64 %0, t; }" : "=r"(a) : "l"(p));
    return a;
}

#define MBARRIER_INIT(a, cnt) \
    asm volatile("mbarrier.init.shared.b64 [%0], %1;" :: "r"(a), "r"(cnt) : "memory")
#define MBARRIER_EXPECT_TX(a, tx) \
    asm volatile("mbarrier.arrive.expect_tx.shared.b64 _, [%0], %1;" :: "r"(a), "r"(tx) : "memory")

__device__ __forceinline__ void bar_wait(uint32_t mbar, uint32_t parity){
    asm volatile("{\n\t.reg .pred P;\n\t"
        "W_%=:\n\t"
        "mbarrier.try_wait.parity.shared.b64 P, [%0], %1;\n\t"
        "@!P bra W_%=;\n\t}"
        :: "r"(mbar), "r"(parity) : "memory");
}

#define TMA2D(dst, map, x, y, mbar) \
    asm volatile("cp.async.bulk.tensor.2d.shared::cta.global.tile.mbarrier::complete_tx::bytes " \
        "[%0], [%1, {%2, %3}], [%4];" \
        :: "r"(dst), "l"(map), "r"(x), "r"(y), "r"(mbar) : "memory")

__device__ __forceinline__ void ldsm4(uint32_t& r0, uint32_t& r1, uint32_t& r2, uint32_t& r3, uint32_t a){
    asm volatile("ldmatrix.sync.aligned.m8n8.x4.shared.b16 {%0,%1,%2,%3}, [%4];"
        : "=r"(r0), "=r"(r1), "=r"(r2), "=r"(r3) : "r"(a));
}
__device__ __forceinline__ void mma_h(float* d, const uint32_t* a, const uint32_t* b){
    asm volatile("mma.sync.aligned.m16n8k16.row.col.f32.f16.f16.f32 "
        "{%0,%1,%2,%3},{%4,%5,%6,%7},{%8,%9},{%0,%1,%2,%3};"
        : "+f"(d[0]), "+f"(d[1]), "+f"(d[2]), "+f"(d[3])
        : "r"(a[0]), "r"(a[1]), "r"(a[2]), "r"(a[3]), "r"(b[0]), "r"(b[1]));
}

// ---------------- split fp32 -> fp16 hi (+ optional exact lo residual) ----------------
__global__ void split16(const float* __restrict__ src, __half* __restrict__ hi,
                        __half* __restrict__ lo, int n4){
    int i = blockIdx.x*blockDim.x + threadIdx.x;
    if (i >= n4) return;
    float4 v = ((const float4*)src)[i];
    __half h0 = __float2half_rn(v.x), h1 = __float2half_rn(v.y);
    __half h2 = __float2half_rn(v.z), h3 = __float2half_rn(v.w);
    __half2* H = (__half2*)hi;
    H[2*i]   = __halves2half2(h0, h1);
    H[2*i+1] = __halves2half2(h2, h3);
    if (lo){
        __half2* L = (__half2*)lo;
        L[2*i]   = __halves2half2(__float2half_rn(v.x - __half2float(h0)),
                                  __float2half_rn(v.y - __half2float(h1)));
        L[2*i+1] = __halves2half2(__float2half_rn(v.z - __half2float(h2)),
                                  __float2half_rn(v.w - __half2float(h3)));
    }
}

// ---------------- TMA-fed fp16x2 HMMA GEMM: C[M,N] = A[M,K]*B[N,K]^T ----------------
// CTA tile 128x128, BK=64 fp16 (128B rows, SW128), 2-stage TMA ring, 8 warps (32x64).
// A exact in (Ah + Al), B rounded to fp16. 2 MMA terms into one fp32 accumulator.
// __launch_bounds__(256, 2): 2 CTAs/SM to cover sync/TMA bubbles (tensor was 75.5% @ occ 1).
#define A_PL 16384
#define STAGE_B (3*A_PL)    // 49152
#define CTRL 1024
#define GSMEM (CTRL + 2*STAGE_B)

__device__ __forceinline__ float gate_act(float v, int g){
    if (g == 0) return __expf(v);
    if (g == 3) return tanhf(v);
    return 1.f/(1.f + __expf(-v));
}

__global__ void __launch_bounds__(256, 2) gemm_f16(
    const __grid_constant__ CUtensorMap tAh, const __grid_constant__ CUtensorMap tAl,
    const __grid_constant__ CUtensorMap tBh,
    const float* __restrict__ bias, float* __restrict__ Cf,
    __half* __restrict__ Ch, __half* __restrict__ Cl,
    int N, int KT, int mode)   // mode 0: fp16 hi/lo out; 1: bias+gate-activation fp32; 2: fp32
{
    extern __shared__ char smem[];
    uint32_t sb = smem_u32(smem);
    const int tid = threadIdx.x;
    const int bm = blockIdx.y, bn = blockIdx.x;

    if (tid == 0){ MBARRIER_INIT(sb, 1); MBARRIER_INIT(sb + 8, 1); }
    __syncthreads();
    if (tid == 0){
        #pragma unroll
        for (int st = 0; st < 2; st++){
            MBARRIER_EXPECT_TX(sb + 8*st, STAGE_B);
            uint32_t base = sb + CTRL + st*STAGE_B;
            TMA2D(base,          &tAh, st*64, bm*128, sb + 8*st);
            TMA2D(base + A_PL,   &tAl, st*64, bm*128, sb + 8*st);
            TMA2D(base + 2*A_PL, &tBh, st*64, bn*128, sb + 8*st);
        }
    }

    const int warp = tid >> 5, ln = tid & 31;
    const int wm = warp >> 1, wn = warp & 1;

    float acc[2][8][4];
    #pragma unroll
    for (int a = 0; a < 2; a++)
        #pragma unroll
        for (int b = 0; b < 8; b++)
            #pragma unroll
            for (int q = 0; q < 4; q++) acc[a][b][q] = 0.f;

    uint32_t par0 = 0, par1 = 0;

    for (int kt = 0; kt < KT; kt++){
        const int st = kt & 1;
        bar_wait(sb + 8*st, st ? par1 : par0);
        if (st) par1 ^= 1; else par0 ^= 1;

        const uint32_t ahB = sb + CTRL + st*STAGE_B;
        const uint32_t alB = ahB + A_PL;
        const uint32_t bhB = ahB + 2*A_PL;

        #pragma unroll
        for (int ks = 0; ks < 4; ks++){
            uint32_t afh[2][4], afl[2][4];
            #pragma unroll
            for (int mt = 0; mt < 2; mt++){
                uint32_t row = wm*32 + mt*16 + ((ln >> 3) & 1)*8 + (ln & 7);
                uint32_t off = row*128 + (ks*16 + (ln >> 4)*8)*2;
                off ^= (off >> 3) & 0x70;
                ldsm4(afh[mt][0], afh[mt][1], afh[mt][2], afh[mt][3], ahB + off);
                ldsm4(afl[mt][0], afl[mt][1], afl[mt][2], afl[mt][3], alB + off);
            }
            uint32_t bfh[8][2];
            #pragma unroll
            for (int p = 0; p < 4; p++){
                uint32_t row = wn*64 + p*16 + (ln >> 4)*8 + (ln & 7);
                uint32_t off = row*128 + (ks*16 + ((ln >> 3) & 1)*8)*2;
                off ^= (off >> 3) & 0x70;
                uint32_t r0, r1, r2, r3;
                ldsm4(r0, r1, r2, r3, bhB + off);
                bfh[2*p][0] = r0; bfh[2*p][1] = r1; bfh[2*p+1][0] = r2; bfh[2*p+1][1] = r3;
            }
            #pragma unroll
            for (int mt = 0; mt < 2; mt++)
                #pragma unroll
                for (int nt = 0; nt < 8; nt++){
                    mma_h(acc[mt][nt], afh[mt], bfh[nt]);   // Ah*Bh
                    mma_h(acc[mt][nt], afl[mt], bfh[nt]);   // Al*Bh
                }
        }
        __syncthreads();
        if (tid == 0 && kt + 2 < KT){
            MBARRIER_EXPECT_TX(sb + 8*st, STAGE_B);
            uint32_t base = sb + CTRL + st*STAGE_B;
            TMA2D(base,          &tAh, (kt+2)*64, bm*128, sb + 8*st);
            TMA2D(base + A_PL,   &tAl, (kt+2)*64, bm*128, sb + 8*st);
            TMA2D(base + 2*A_PL, &tBh, (kt+2)*64, bn*128, sb + 8*st);
        }
    }

    // ---- epilogue ----
    const int orow = bm*128 + wm*32;
    const int ocol = bn*128 + wn*64;
    #pragma unroll
    for (int mt = 0; mt < 2; mt++)
        #pragma unroll
        for (int nt = 0; nt < 8; nt++){
            float* a = acc[mt][nt];
            int r0 = orow + mt*16 + (ln >> 2);
            int c0 = ocol + nt*8 + (ln & 3)*2;
            if (mode == 0){
                #pragma unroll
                for (int q = 0; q < 2; q++){
                    size_t o = (size_t)(r0 + q*8)*N + c0;
                    __half h0 = __float2half_rn(a[2*q]);
                    __half h1 = __float2half_rn(a[2*q+1]);
                    *(__half2*)(Ch + o) = __halves2half2(h0, h1);
                    *(__half2*)(Cl + o) = __halves2half2(
                        __float2half_rn(a[2*q]   - __half2float(h0)),
                        __float2half_rn(a[2*q+1] - __half2float(h1)));
                }
            } else if (mode == 1){
                int g = (c0 >> 9) & 3;
                float b0 = bias[c0], b1 = bias[c0+1];
                float v00 = gate_act(a[0] + b0, g), v01 = gate_act(a[1] + b1, g);
                float v10 = gate_act(a[2] + b0, g), v11 = gate_act(a[3] + b1, g);
                *(float2*)(Cf + (size_t)r0*N + c0)     = float2{v00, v01};
                *(float2*)(Cf + (size_t)(r0+8)*N + c0) = float2{v10, v11};
            } else {
                *(float2*)(Cf + (size_t)r0*N + c0)     = float2{a[0], a[1]};
                *(float2*)(Cf + (size_t)(r0+8)*N + c0) = float2{a[2], a[3]};
            }
        }
}

// ---------------- scan pass 1: per-chunk (A = prod f, B) — gates pre-activated ----------------
__global__ void scan_pass1(){
    int blk = blockIdx.x;
    int ch = blk / BH_, bh = blk % BH_;
    int b = bh / NH_, h = bh % NH_;
    int d = threadIdx.x;
    float A = 1.f, Bv = 0.f;
    for (int s = 0; s < CH_; s++){
        int tok = b*L_ + ch*CH_ + s;
        size_t base = (size_t)tok*GN_ + h*(4*HD_) + d;
        float ig = g_gates[base], f = g_gates[base + HD_], cd = g_gates[base + 3*HD_];
        Bv = f*Bv + ig*cd;
        A *= f;
    }
    g_scanA[ch*BHD_ + bh*HD_ + d] = A;
    g_scanB[ch*BHD_ + bh*HD_ + d] = Bv;
}

// ---------------- scan pass 2: sequential chunk composition ----------------
__global__ void scan_pass2(){
    int idx = blockIdx.x*blockDim.x + threadIdx.x;
    float c = 0.f;
    for (int ch = 0; ch < NCH_; ch++){
        g_carry[ch*BHD_ + idx] = c;
        c = g_scanA[ch*BHD_ + idx]*c + g_scanB[ch*BHD_ + idx];
    }
}

// ---------------- scan pass 3: replay + RMS norm + h (fp16 hi/lo out) ----------------
__global__ void scan_pass3(const float* __restrict__ rms_w){
    __shared__ float red[16];
    __shared__ float s_norm;
    int blk = blockIdx.x;
    int ch = blk / BH_, bh = blk % BH_;
    int b = bh / NH_, h = bh % NH_;
    int d = threadIdx.x;
    int warp = d >> 5, lane = d & 31;
    float c = g_carry[ch*BHD_ + bh*HD_ + d];
    float w = rms_w[d];
    for (int s = 0; s < CH_; s++){
        int tok = b*L_ + ch*CH_ + s;
        size_t base = (size_t)tok*GN_ + h*(4*HD_) + d;
        float ig = g_gates[base],          f  = g_gates[base + HD_];
        float og = g_gates[base + 2*HD_],  cd = g_gates[base + 3*HD_];
        c = f*c + ig*cd;
        float sq = c*c;
        #pragma unroll
        for (int o = 16; o; o >>= 1) sq += __shfl_xor_sync(0xffffffffu, sq, o);
        if (!lane) red[warp] = sq;
        __syncthreads();
        if (warp == 0){
            float vv = (lane < 16) ? red[lane] : 0.f;
            #pragma unroll
            for (int o = 8; o; o >>= 1) vv += __shfl_xor_sync(0xffffffffu, vv, o);
            if (!lane) s_norm = rsqrtf(vv*(1.f/HD_) + EPS_);
        }
        __syncthreads();
        float cn = c * s_norm * w;
        float hv = og * tanhf(cn);
        size_t ho = (size_t)tok*HID_ + h*HD_ + d;
        __half hh = __float2half_rn(hv);
        g_hh[ho] = hh;
        g_hl[ho] = __float2half_rn(hv - __half2float(hh));
    }
}

// ---------------- host side ----------------
typedef CUresult (*PFN_encode_t)(CUtensorMap*, CUtensorMapDataType, cuuint32_t, void*,
                                 const cuuint64_t*, const cuuint64_t*, const cuuint32_t*,
                                 const cuuint32_t*, CUtensorMapInterleave, CUtensorMapSwizzle,
                                 CUtensorMapL2promotion, CUtensorMapFloatOOBfill);

static void enc_map16(PFN_encode_t fn, CUtensorMap* m, void* gaddr, uint64_t rows){
    cuuint64_t dims[2]    = {KROW_, rows};
    cuuint64_t strides[1] = {KROW_ * 2};
    cuuint32_t box[2]     = {64u, 128u};
    cuuint32_t es[2]      = {1u, 1u};
    fn(m, CU_TENSOR_MAP_DATA_TYPE_FLOAT16, 2, gaddr, dims, strides, box, es,
       CU_TENSOR_MAP_INTERLEAVE_NONE, CU_TENSOR_MAP_SWIZZLE_128B,
       CU_TENSOR_MAP_L2_PROMOTION_L2_128B, CU_TENSOR_MAP_FLOAT_OOB_FILL_NONE);
}

extern "C" void kernel_launch(void* const* d_in, const int* in_sizes, int n_in,
                              void* d_out, int out_size){
    const float* x      = (const float*)d_in[0];
    const float* W_in   = (const float*)d_in[1];
    const float* W_gate = (const float*)d_in[2];
    const float* b_gate = (const float*)d_in[3];
    const float* rms_w  = (const float*)d_in[4];
    const float* W_out  = (const float*)d_in[5];

    void *xh, *xl, *wih, *wgh, *woh, *xph, *xpl, *gts, *hh, *hl;
    cudaGetSymbolAddress(&xh,  g_xh);   cudaGetSymbolAddress(&xl,  g_xl);
    cudaGetSymbolAddress(&wih, g_Wih);  cudaGetSymbolAddress(&wgh, g_Wgh);
    cudaGetSymbolAddress(&woh, g_Woh);
    cudaGetSymbolAddress(&xph, g_xph);  cudaGetSymbolAddress(&xpl, g_xpl);
    cudaGetSymbolAddress(&gts, g_gates);
    cudaGetSymbolAddress(&hh,  g_hh);   cudaGetSymbolAddress(&hl,  g_hl);

    void* pfn = nullptr;
    cudaDriverEntryPointQueryResult qr;
    cudaGetDriverEntryPoint("cuTensorMapEncodeTiled", &pfn, cudaEnableDefault, &qr);
    PFN_encode_t enc = (PFN_encode_t)pfn;

    CUtensorMap mXh, mXl, mWih, mXph, mXpl, mWgh, mHh, mHl, mWoh;
    enc_map16(enc, &mXh,  xh,  NTOK_);  enc_map16(enc, &mXl,  xl,  NTOK_);
    enc_map16(enc, &mWih, wih, HID_);
    enc_map16(enc, &mXph, xph, NTOK_);  enc_map16(enc, &mXpl, xpl, NTOK_);
    enc_map16(enc, &mWgh, wgh, GN_);
    enc_map16(enc, &mHh,  hh,  NTOK_);  enc_map16(enc, &mHl,  hl,  NTOK_);
    enc_map16(enc, &mWoh, woh, DIM_);

    cudaFuncSetAttribute(gemm_f16, cudaFuncAttributeMaxDynamicSharedMemorySize, GSMEM);

    int n4;
    n4 = NTOK_*DIM_/4; split16<<<(n4+255)/256, 256>>>(x,      (__half*)xh,  (__half*)xl, n4); // 0
    n4 = HID_*DIM_/4;  split16<<<(n4+255)/256, 256>>>(W_in,   (__half*)wih, nullptr, n4);     // 1
    n4 = GN_*HID_/4;   split16<<<(n4+255)/256, 256>>>(W_gate, (__half*)wgh, nullptr, n4);     // 2

    // 3: G1: xp = x @ W_in^T -> fp16 hi/lo  (profiled slot)
    gemm_f16<<<dim3(HID_/128, NTOK_/128), 256, GSMEM>>>(
        mXh, mXl, mWih, nullptr, nullptr,
        (__half*)xph, (__half*)xpl, HID_, KROW_/64, 0);

    n4 = DIM_*HID_/4;  split16<<<(n4+255)/256, 256>>>(W_out, (__half*)woh, nullptr, n4);      // 4

    // G2: gates = act(xp @ W_gate^T + b_gate) -> fp32
    gemm_f16<<<dim3(GN_/128, NTOK_/128), 256, GSMEM>>>(
        mXph, mXpl, mWgh, b_gate, (float*)gts,
        nullptr, nullptr, GN_, KROW_/64, 1);

    // chunked parallel scan
    scan_pass1<<<NCH_*BH_, HD_>>>();
    scan_pass2<<<BHD_/256, 256>>>();
    scan_pass3<<<NCH_*BH_, HD_>>>(rms_w);

    // G3: out = h @ W_out^T -> fp32 to d_out
    gemm_f16<<<dim3(DIM_/128, NTOK_/128), 256, GSMEM>>>(
        mHh, mHl, mWoh, nullptr, (float*)d_out,
        nullptr, nullptr, DIM_, KROW_/64, 2);
}

// round 11
// speedup vs baseline: 4.9601x; 1.0094x over previous
#include <cuda.h>
#include <cuda_runtime.h>
#include <cuda_fp16.h>
#include <stdint.h>

#define DIM_  2048
#define HID_  2048
#define NH_   4
#define HD_   512
#define B_    4
#define L_    2048
#define NTOK_ 8192
#define GN_   8192
#define EPS_  1e-6f
#define CH_   64
#define NCH_  32
#define BH_   16
#define BHD_  (BH_*HD_)
#define KROW_ 2048

// ---------------- device scratch ----------------
__device__ __align__(1024) __half g_xh[(size_t)NTOK_*DIM_],  g_xl[(size_t)NTOK_*DIM_];
__device__ __align__(1024) __half g_Wih[(size_t)HID_*DIM_];
__device__ __align__(1024) __half g_Wgh[(size_t)GN_*HID_];
__device__ __align__(1024) __half g_Woh[(size_t)DIM_*HID_];
__device__ __align__(1024) __half g_xph[(size_t)NTOK_*HID_], g_xpl[(size_t)NTOK_*HID_];
__device__ __align__(1024) float  g_gates[(size_t)NTOK_*GN_];   // activated gates
__device__ __align__(1024) __half g_hh[(size_t)NTOK_*HID_];
__device__ float g_scanA[NCH_*BHD_], g_scanB[NCH_*BHD_], g_carry[NCH_*BHD_];

// ---------------- helpers ----------------
__device__ __forceinline__ uint32_t smem_u32(const void* p){
    uint32_t a;
    asm("{ .reg .u64 t; cvta.to.shared.u64 t, %1; cvt.u32.u64 %0, t; }" : "=r"(a) : "l"(p));
    return a;
}

#define MBARRIER_INIT(a, cnt) \
    asm volatile("mbarrier.init.shared.b64 [%0], %1;" :: "r"(a), "r"(cnt) : "memory")
#define MBARRIER_EXPECT_TX(a, tx) \
    asm volatile("mbarrier.arrive.expect_tx.shared.b64 _, [%0], %1;" :: "r"(a), "r"(tx) : "memory")

__device__ __forceinline__ void bar_wait(uint32_t mbar, uint32_t parity){
    asm volatile("{\n\t.reg .pred P;\n\t"
        "W_%=:\n\t"
        "mbarrier.try_wait.parity.shared.b64 P, [%0], %1;\n\t"
        "@!P bra W_%=;\n\t}"
        :: "r"(mbar), "r"(parity) : "memory");
}

#define TMA2D(dst, map, x, y, mbar) \
    asm volatile("cp.async.bulk.tensor.2d.shared::cta.global.tile.mbarrier::complete_tx::bytes " \
        "[%0], [%1, {%2, %3}], [%4];" \
        :: "r"(dst), "l"(map), "r"(x), "r"(y), "r"(mbar) : "memory")

__device__ __forceinline__ void ldsm4(uint32_t& r0, uint32_t& r1, uint32_t& r2, uint32_t& r3, uint32_t a){
    asm volatile("ldmatrix.sync.aligned.m8n8.x4.shared.b16 {%0,%1,%2,%3}, [%4];"
        : "=r"(r0), "=r"(r1), "=r"(r2), "=r"(r3) : "r"(a));
}
__device__ __forceinline__ void mma_h(float* d, const uint32_t* a, const uint32_t* b){
    asm volatile("mma.sync.aligned.m16n8k16.row.col.f32.f16.f16.f32 "
        "{%0,%1,%2,%3},{%4,%5,%6,%7},{%8,%9},{%0,%1,%2,%3};"
        : "+f"(d[0]), "+f"(d[1]), "+f"(d[2]), "+f"(d[3])
        : "r"(a[0]), "r"(a[1]), "r"(a[2]), "r"(a[3]), "r"(b[0]), "r"(b[1]));
}

// ---------------- split fp32 -> fp16 hi (+ optional exact lo residual) ----------------
__global__ void split16(const float* __restrict__ src, __half* __restrict__ hi,
                        __half* __restrict__ lo, int n4){
    int i = blockIdx.x*blockDim.x + threadIdx.x;
    if (i >= n4) return;
    float4 v = ((const float4*)src)[i];
    __half h0 = __float2half_rn(v.x), h1 = __float2half_rn(v.y);
    __half h2 = __float2half_rn(v.z), h3 = __float2half_rn(v.w);
    __half2* H = (__half2*)hi;
    H[2*i]   = __halves2half2(h0, h1);
    H[2*i+1] = __halves2half2(h2, h3);
    if (lo){
        __half2* L = (__half2*)lo;
        L[2*i]   = __halves2half2(__float2half_rn(v.x - __half2float(h0)),
                                  __float2half_rn(v.y - __half2float(h1)));
        L[2*i+1] = __halves2half2(__float2half_rn(v.z - __half2float(h2)),
                                  __float2half_rn(v.w - __half2float(h3)));
    }
}

// ---------------- TMA-fed fp16 HMMA GEMM: C[M,N] = A[M,K]*B[N,K]^T ----------------
// CTA tile 128x128, BK=64 fp16 (128B rows, SW128), 2-stage TMA ring, 8 warps (32x64), occ 2.
// nterms==2: A exact as (Ah + Al), 2 MMA terms. nterms==1: plain fp16 A, 1 MMA term.
#define A_PL 16384
#define STAGE_B (3*A_PL)    // 49152 (layout reserves Al slot even when unused)
#define CTRL 1024
#define GSMEM (CTRL + 2*STAGE_B)

__device__ __forceinline__ float gate_act(float v, int g){
    if (g == 0) return __expf(v);
    if (g == 3) return tanhf(v);
    return 1.f/(1.f + __expf(-v));
}

__global__ void __launch_bounds__(256, 2) gemm_f16(
    const __grid_constant__ CUtensorMap tAh, const __grid_constant__ CUtensorMap tAl,
    const __grid_constant__ CUtensorMap tBh,
    const float* __restrict__ bias, float* __restrict__ Cf,
    __half* __restrict__ Ch, __half* __restrict__ Cl,
    int N, int KT, int mode, int nterms)
{
    extern __shared__ char smem[];
    uint32_t sb = smem_u32(smem);
    const int tid = threadIdx.x;
    const int bm = blockIdx.y, bn = blockIdx.x;
    const uint32_t exp_bytes = (nterms == 2) ? 3*A_PL : 2*A_PL;

    if (tid == 0){ MBARRIER_INIT(sb, 1); MBARRIER_INIT(sb + 8, 1); }
    __syncthreads();
    if (tid == 0){
        #pragma unroll
        for (int st = 0; st < 2; st++){
            MBARRIER_EXPECT_TX(sb + 8*st, exp_bytes);
            uint32_t base = sb + CTRL + st*STAGE_B;
            TMA2D(base,          &tAh, st*64, bm*128, sb + 8*st);
            if (nterms == 2) TMA2D(base + A_PL, &tAl, st*64, bm*128, sb + 8*st);
            TMA2D(base + 2*A_PL, &tBh, st*64, bn*128, sb + 8*st);
        }
    }

    const int warp = tid >> 5, ln = tid & 31;
    const int wm = warp >> 1, wn = warp & 1;

    float acc[2][8][4];
    #pragma unroll
    for (int a = 0; a < 2; a++)
        #pragma unroll
        for (int b = 0; b < 8; b++)
            #pragma unroll
            for (int q = 0; q < 4; q++) acc[a][b][q] = 0.f;

    uint32_t par0 = 0, par1 = 0;

    for (int kt = 0; kt < KT; kt++){
        const int st = kt & 1;
        bar_wait(sb + 8*st, st ? par1 : par0);
        if (st) par1 ^= 1; else par0 ^= 1;

        const uint32_t ahB = sb + CTRL + st*STAGE_B;
        const uint32_t alB = ahB + A_PL;
        const uint32_t bhB = ahB + 2*A_PL;

        #pragma unroll
        for (int ks = 0; ks < 4; ks++){
            uint32_t afh[2][4], afl[2][4];
            #pragma unroll
            for (int mt = 0; mt < 2; mt++){
                uint32_t row = wm*32 + mt*16 + ((ln >> 3) & 1)*8 + (ln & 7);
                uint32_t off = row*128 + (ks*16 + (ln >> 4)*8)*2;
                off ^= (off >> 3) & 0x70;
                ldsm4(afh[mt][0], afh[mt][1], afh[mt][2], afh[mt][3], ahB + off);
                if (nterms == 2)
                    ldsm4(afl[mt][0], afl[mt][1], afl[mt][2], afl[mt][3], alB + off);
            }
            uint32_t bfh[8][2];
            #pragma unroll
            for (int p = 0; p < 4; p++){
                uint32_t row = wn*64 + p*16 + (ln >> 4)*8 + (ln & 7);
                uint32_t off = row*128 + (ks*16 + ((ln >> 3) & 1)*8)*2;
                off ^= (off >> 3) & 0x70;
                uint32_t r0, r1, r2, r3;
                ldsm4(r0, r1, r2, r3, bhB + off);
                bfh[2*p][0] = r0; bfh[2*p][1] = r1; bfh[2*p+1][0] = r2; bfh[2*p+1][1] = r3;
            }
            #pragma unroll
            for (int mt = 0; mt < 2; mt++)
                #pragma unroll
                for (int nt = 0; nt < 8; nt++){
                    mma_h(acc[mt][nt], afh[mt], bfh[nt]);                     // Ah*Bh
                    if (nterms == 2) mma_h(acc[mt][nt], afl[mt], bfh[nt]);    // Al*Bh
                }
        }
        __syncthreads();
        if (tid == 0 && kt + 2 < KT){
            MBARRIER_EXPECT_TX(sb + 8*st, exp_bytes);
            uint32_t base = sb + CTRL + st*STAGE_B;
            TMA2D(base,          &tAh, (kt+2)*64, bm*128, sb + 8*st);
            if (nterms == 2) TMA2D(base + A_PL, &tAl, (kt+2)*64, bm*128, sb + 8*st);
            TMA2D(base + 2*A_PL, &tBh, (kt+2)*64, bn*128, sb + 8*st);
        }
    }

    // ---- epilogue ----
    const int orow = bm*128 + wm*32;
    const int ocol = bn*128 + wn*64;
    #pragma unroll
    for (int mt = 0; mt < 2; mt++)
        #pragma unroll
        for (int nt = 0; nt < 8; nt++){
            float* a = acc[mt][nt];
            int r0 = orow + mt*16 + (ln >> 2);
            int c0 = ocol + nt*8 + (ln & 3)*2;
            if (mode == 0){
                #pragma unroll
                for (int q = 0; q < 2; q++){
                    size_t o = (size_t)(r0 + q*8)*N + c0;
                    __half h0 = __float2half_rn(a[2*q]);
                    __half h1 = __float2half_rn(a[2*q+1]);
                    *(__half2*)(Ch + o) = __halves2half2(h0, h1);
                    *(__half2*)(Cl + o) = __halves2half2(
                        __float2half_rn(a[2*q]   - __half2float(h0)),
                        __float2half_rn(a[2*q+1] - __half2float(h1)));
                }
            } else if (mode == 1){
                int g = (c0 >> 9) & 3;
                float b0 = bias[c0], b1 = bias[c0+1];
                float v00 = gate_act(a[0] + b0, g), v01 = gate_act(a[1] + b1, g);
                float v10 = gate_act(a[2] + b0, g), v11 = gate_act(a[3] + b1, g);
                *(float2*)(Cf + (size_t)r0*N + c0)     = float2{v00, v01};
                *(float2*)(Cf + (size_t)(r0+8)*N + c0) = float2{v10, v11};
            } else {
                *(float2*)(Cf + (size_t)r0*N + c0)     = float2{a[0], a[1]};
                *(float2*)(Cf + (size_t)(r0+8)*N + c0) = float2{a[2], a[3]};
            }
        }
}

// ---------------- scan pass 1: per-chunk (A = prod f, B) — gates pre-activated ----------------
__global__ void scan_pass1(){
    int blk = blockIdx.x;
    int ch = blk / BH_, bh = blk % BH_;
    int b = bh / NH_, h = bh % NH_;
    int d = threadIdx.x;
    float A = 1.f, Bv = 0.f;
    for (int s = 0; s < CH_; s++){
        int tok = b*L_ + ch*CH_ + s;
        size_t base = (size_t)tok*GN_ + h*(4*HD_) + d;
        float ig = g_gates[base], f = g_gates[base + HD_], cd = g_gates[base + 3*HD_];
        Bv = f*Bv + ig*cd;
        A *= f;
    }
    g_scanA[ch*BHD_ + bh*HD_ + d] = A;
    g_scanB[ch*BHD_ + bh*HD_ + d] = Bv;
}

// ---------------- scan pass 2: sequential chunk composition ----------------
__global__ void scan_pass2(){
    int idx = blockIdx.x*blockDim.x + threadIdx.x;
    float c = 0.f;
    for (int ch = 0; ch < NCH_; ch++){
        g_carry[ch*BHD_ + idx] = c;
        c = g_scanA[ch*BHD_ + idx]*c + g_scanB[ch*BHD_ + idx];
    }
}

// ---------------- scan pass 3: replay + RMS norm + h (fp16 out) ----------------
__global__ void scan_pass3(const float* __restrict__ rms_w){
    __shared__ float red[16];
    __shared__ float s_norm;
    int blk = blockIdx.x;
    int ch = blk / BH_, bh = blk % BH_;
    int b = bh / NH_, h = bh % NH_;
    int d = threadIdx.x;
    int warp = d >> 5, lane = d & 31;
    float c = g_carry[ch*BHD_ + bh*HD_ + d];
    float w = rms_w[d];
    for (int s = 0; s < CH_; s++){
        int tok = b*L_ + ch*CH_ + s;
        size_t base = (size_t)tok*GN_ + h*(4*HD_) + d;
        float ig = g_gates[base],          f  = g_gates[base + HD_];
        float og = g_gates[base + 2*HD_],  cd = g_gates[base + 3*HD_];
        c = f*c + ig*cd;
        float sq = c*c;
        #pragma unroll
        for (int o = 16; o; o >>= 1) sq += __shfl_xor_sync(0xffffffffu, sq, o);
        if (!lane) red[warp] = sq;
        __syncthreads();
        if (warp == 0){
            float vv = (lane < 16) ? red[lane] : 0.f;
            #pragma unroll
            for (int o = 8; o; o >>= 1) vv += __shfl_xor_sync(0xffffffffu, vv, o);
            if (!lane) s_norm = rsqrtf(vv*(1.f/HD_) + EPS_);
        }
        __syncthreads();
        float cn = c * s_norm * w;
        float hv = og * tanhf(cn);
        g_hh[(size_t)tok*HID_ + h*HD_ + d] = __float2half_rn(hv);
    }
}

// ---------------- host side ----------------
typedef CUresult (*PFN_encode_t)(CUtensorMap*, CUtensorMapDataType, cuuint32_t, void*,
                                 const cuuint64_t*, const cuuint64_t*, const cuuint32_t*,
                                 const cuuint32_t*, CUtensorMapInterleave, CUtensorMapSwizzle,
                                 CUtensorMapL2promotion, CUtensorMapFloatOOBfill);

static void enc_map16(PFN_encode_t fn, CUtensorMap* m, void* gaddr, uint64_t rows){
    cuuint64_t dims[2]    = {KROW_, rows};
    cuuint64_t strides[1] = {KROW_ * 2};
    cuuint32_t box[2]     = {64u, 128u};
    cuuint32_t es[2]      = {1u, 1u};
    fn(m, CU_TENSOR_MAP_DATA_TYPE_FLOAT16, 2, gaddr, dims, strides, box, es,
       CU_TENSOR_MAP_INTERLEAVE_NONE, CU_TENSOR_MAP_SWIZZLE_128B,
       CU_TENSOR_MAP_L2_PROMOTION_L2_128B, CU_TENSOR_MAP_FLOAT_OOB_FILL_NONE);
}

extern "C" void kernel_launch(void* const* d_in, const int* in_sizes, int n_in,
                              void* d_out, int out_size){
    const float* x      = (const float*)d_in[0];
    const float* W_in   = (const float*)d_in[1];
    const float* W_gate = (const float*)d_in[2];
    const float* b_gate = (const float*)d_in[3];
    const float* rms_w  = (const float*)d_in[4];
    const float* W_out  = (const float*)d_in[5];

    void *xh, *xl, *wih, *wgh, *woh, *xph, *xpl, *gts, *hh;
    cudaGetSymbolAddress(&xh,  g_xh);   cudaGetSymbolAddress(&xl,  g_xl);
    cudaGetSymbolAddress(&wih, g_Wih);  cudaGetSymbolAddress(&wgh, g_Wgh);
    cudaGetSymbolAddress(&woh, g_Woh);
    cudaGetSymbolAddress(&xph, g_xph);  cudaGetSymbolAddress(&xpl, g_xpl);
    cudaGetSymbolAddress(&gts, g_gates);
    cudaGetSymbolAddress(&hh,  g_hh);

    void* pfn = nullptr;
    cudaDriverEntryPointQueryResult qr;
    cudaGetDriverEntryPoint("cuTensorMapEncodeTiled", &pfn, cudaEnableDefault, &qr);
    PFN_encode_t enc = (PFN_encode_t)pfn;

    CUtensorMap mXh, mXl, mWih, mXph, mXpl, mWgh, mHh, mWoh;
    enc_map16(enc, &mXh,  xh,  NTOK_);  enc_map16(enc, &mXl,  xl,  NTOK_);
    enc_map16(enc, &mWih, wih, HID_);
    enc_map16(enc, &mXph, xph, NTOK_);  enc_map16(enc, &mXpl, xpl, NTOK_);
    enc_map16(enc, &mWgh, wgh, GN_);
    enc_map16(enc, &mHh,  hh,  NTOK_);
    enc_map16(enc, &mWoh, woh, DIM_);

    cudaFuncSetAttribute(gemm_f16, cudaFuncAttributeMaxDynamicSharedMemorySize, GSMEM);

    int n4;
    n4 = NTOK_*DIM_/4; split16<<<(n4+255)/256, 256>>>(x,      (__half*)xh,  (__half*)xl, n4); // 0
    n4 = HID_*DIM_/4;  split16<<<(n4+255)/256, 256>>>(W_in,   (__half*)wih, nullptr, n4);     // 1
    n4 = GN_*HID_/4;   split16<<<(n4+255)/256, 256>>>(W_gate, (__half*)wgh, nullptr, n4);     // 2

    // 3: G1: xp = x @ W_in^T -> fp16 hi/lo  (2-term exact A; profiled slot)
    gemm_f16<<<dim3(HID_/128, NTOK_/128), 256, GSMEM>>>(
        mXh, mXl, mWih, nullptr, nullptr,
        (__half*)xph, (__half*)xpl, HID_, KROW_/64, 0, 2);

    n4 = DIM_*HID_/4;  split16<<<(n4+255)/256, 256>>>(W_out, (__half*)woh, nullptr, n4);      // 4

    // G2: gates = act(xp_hi @ W_gate^T + b_gate) -> fp32  (1-term fp16)
    gemm_f16<<<dim3(GN_/128, NTOK_/128), 256, GSMEM>>>(
        mXph, mXph, mWgh, b_gate, (float*)gts,
        nullptr, nullptr, GN_, KROW_/64, 1, 1);

    // chunked parallel scan
    scan_pass1<<<NCH_*BH_, HD_>>>();
    scan_pass2<<<BHD_/256, 256>>>();
    scan_pass3<<<NCH_*BH_, HD_>>>(rms_w);

    // G3: out = h @ W_out^T -> fp32 to d_out  (1-term fp16)
    gemm_f16<<<dim3(DIM_/128, NTOK_/128), 256, GSMEM>>>(
        mHh, mHh, mWoh, nullptr, (float*)d_out,
        nullptr, nullptr, DIM_, KROW_/64, 2, 1);
}

// round 12
// speedup vs baseline: 7.3989x; 1.4917x over previous
#include <cuda.h>
#include <cuda_runtime.h>
#include <cuda_fp16.h>
#include <stdint.h>

#define DIM_  2048
#define HID_  2048
#define NH_   4
#define HD_   512
#define B_    4
#define L_    2048
#define NTOK_ 8192
#define GN_   8192
#define EPS_  1e-6f
#define CH_   64
#define NCH_  32
#define BH_   16
#define BHD_  (BH_*HD_)
#define KROW_ 2048

// ---------------- device scratch ----------------
__device__ __align__(1024) __half g_xh[(size_t)NTOK_*DIM_],  g_xl[(size_t)NTOK_*DIM_];
__device__ __align__(1024) __half g_Wih[(size_t)HID_*DIM_];
__device__ __align__(1024) __half g_Wgh[(size_t)GN_*HID_];
__device__ __align__(1024) __half g_Woh[(size_t)DIM_*HID_];
__device__ __align__(1024) __half g_xph[(size_t)NTOK_*HID_], g_xpl[(size_t)NTOK_*HID_];
__device__ __align__(1024) float  g_gates[(size_t)NTOK_*GN_];   // activated gates
__device__ __align__(1024) __half g_hh[(size_t)NTOK_*HID_];
__device__ float g_scanA[NCH_*BHD_], g_scanB[NCH_*BHD_], g_carry[NCH_*BHD_];

// ---------------- helpers ----------------
__device__ __forceinline__ uint32_t smem_u32(const void* p){
    uint32_t a;
    asm("{ .reg .u64 t; cvta.to.shared.u64 t, %1; cvt.u32.u64 %0, t; }" : "=r"(a) : "l"(p));
    return a;
}

#define MBARRIER_INIT(a, cnt) \
    asm volatile("mbarrier.init.shared.b64 [%0], %1;" :: "r"(a), "r"(cnt) : "memory")
#define MBARRIER_EXPECT_TX(a, tx) \
    asm volatile("mbarrier.arrive.expect_tx.shared.b64 _, [%0], %1;" :: "r"(a), "r"(tx) : "memory")

__device__ __forceinline__ void bar_wait(uint32_t mbar, uint32_t parity){
    asm volatile("{\n\t.reg .pred P;\n\t"
        "W_%=:\n\t"
        "mbarrier.try_wait.parity.shared.b64 P, [%0], %1;\n\t"
        "@!P bra W_%=;\n\t}"
        :: "r"(mbar), "r"(parity) : "memory");
}

#define TMA2D(dst, map, x, y, mbar) \
    asm volatile("cp.async.bulk.tensor.2d.shared::cta.global.tile.mbarrier::complete_tx::bytes " \
        "[%0], [%1, {%2, %3}], [%4];" \
        :: "r"(dst), "l"(map), "r"(x), "r"(y), "r"(mbar) : "memory")

__device__ __forceinline__ void ldsm4(uint32_t& r0, uint32_t& r1, uint32_t& r2, uint32_t& r3, uint32_t a){
    asm volatile("ldmatrix.sync.aligned.m8n8.x4.shared.b16 {%0,%1,%2,%3}, [%4];"
        : "=r"(r0), "=r"(r1), "=r"(r2), "=r"(r3) : "r"(a));
}
__device__ __forceinline__ void mma_h(float* d, const uint32_t* a, const uint32_t* b){
    asm volatile("mma.sync.aligned.m16n8k16.row.col.f32.f16.f16.f32 "
        "{%0,%1,%2,%3},{%4,%5,%6,%7},{%8,%9},{%0,%1,%2,%3};"
        : "+f"(d[0]), "+f"(d[1]), "+f"(d[2]), "+f"(d[3])
        : "r"(a[0]), "r"(a[1]), "r"(a[2]), "r"(a[3]), "r"(b[0]), "r"(b[1]));
}

// ---------------- split fp32 -> fp16 hi (+ optional exact lo residual) ----------------
__global__ void split16(const float* __restrict__ src, __half* __restrict__ hi,
                        __half* __restrict__ lo, int n4){
    int i = blockIdx.x*blockDim.x + threadIdx.x;
    if (i >= n4) return;
    float4 v = ((const float4*)src)[i];
    __half h0 = __float2half_rn(v.x), h1 = __float2half_rn(v.y);
    __half h2 = __float2half_rn(v.z), h3 = __float2half_rn(v.w);
    __half2* H = (__half2*)hi;
    H[2*i]   = __halves2half2(h0, h1);
    H[2*i+1] = __halves2half2(h2, h3);
    if (lo){
        __half2* L = (__half2*)lo;
        L[2*i]   = __halves2half2(__float2half_rn(v.x - __half2float(h0)),
                                  __float2half_rn(v.y - __half2float(h1)));
        L[2*i+1] = __halves2half2(__float2half_rn(v.z - __half2float(h2)),
                                  __float2half_rn(v.w - __half2float(h3)));
    }
}

// ---------------- TMA-fed fp16 HMMA GEMM: C[M,N] = A[M,K]*B[N,K]^T ----------------
// CTA tile 128x128, BK=64 fp16 (128B rows, SW128), 8 warps (32x64), occ 2.
// Template: NT=2 -> A exact (Ah+Al), 2 MMA terms, NSTG-stage ring of 48KB stages.
//           NT=1 -> plain fp16 A, 1 MMA term, NSTG-stage ring of 32KB stages.
#define A_PL 16384
#define CTRL 1024

__device__ __forceinline__ float gate_act(float v, int g){
    if (g == 0) return __expf(v);
    if (g == 3) return tanhf(v);
    return 1.f/(1.f + __expf(-v));
}

template<int NT, int NSTG>
__global__ void __launch_bounds__(256, 2) gemm_f16(
    const __grid_constant__ CUtensorMap tAh, const __grid_constant__ CUtensorMap tAl,
    const __grid_constant__ CUtensorMap tBh,
    const float* __restrict__ bias, float* __restrict__ Cf,
    __half* __restrict__ Ch, __half* __restrict__ Cl,
    int N, int KT, int mode)
{
    constexpr uint32_t STG_B = (NT + 1) * A_PL;     // A (+Al) + B
    constexpr uint32_t B_OFF = NT * A_PL;
    extern __shared__ char smem[];
    uint32_t sb = smem_u32(smem);
    const int tid = threadIdx.x;
    const int bm = blockIdx.y, bn = blockIdx.x;

    if (tid == 0){
        #pragma unroll
        for (int s = 0; s < NSTG; s++) MBARRIER_INIT(sb + 8*s, 1);
    }
    __syncthreads();
    if (tid == 0){
        #pragma unroll
        for (int st = 0; st < NSTG; st++){
            MBARRIER_EXPECT_TX(sb + 8*st, STG_B);
            uint32_t base = sb + CTRL + st*STG_B;
            TMA2D(base,          &tAh, st*64, bm*128, sb + 8*st);
            if (NT == 2) TMA2D(base + A_PL, &tAl, st*64, bm*128, sb + 8*st);
            TMA2D(base + B_OFF,  &tBh, st*64, bn*128, sb + 8*st);
        }
    }

    const int warp = tid >> 5, ln = tid & 31;
    const int wm = warp >> 1, wn = warp & 1;

    float acc[2][8][4];
    #pragma unroll
    for (int a = 0; a < 2; a++)
        #pragma unroll
        for (int b = 0; b < 8; b++)
            #pragma unroll
            for (int q = 0; q < 4; q++) acc[a][b][q] = 0.f;

    int st = 0, ph = 0;

    for (int kt = 0; kt < KT; kt++){
        bar_wait(sb + 8*st, ph);

        const uint32_t ahB = sb + CTRL + st*STG_B;
        const uint32_t alB = ahB + A_PL;
        const uint32_t bhB = ahB + B_OFF;

        #pragma unroll
        for (int ks = 0; ks < 4; ks++){
            uint32_t afh[2][4], afl[2][4];
            #pragma unroll
            for (int mt = 0; mt < 2; mt++){
                uint32_t row = wm*32 + mt*16 + ((ln >> 3) & 1)*8 + (ln & 7);
                uint32_t off = row*128 + (ks*16 + (ln >> 4)*8)*2;
                off ^= (off >> 3) & 0x70;
                ldsm4(afh[mt][0], afh[mt][1], afh[mt][2], afh[mt][3], ahB + off);
                if (NT == 2)
                    ldsm4(afl[mt][0], afl[mt][1], afl[mt][2], afl[mt][3], alB + off);
            }
            uint32_t bfh[8][2];
            #pragma unroll
            for (int p = 0; p < 4; p++){
                uint32_t row = wn*64 + p*16 + (ln >> 4)*8 + (ln & 7);
                uint32_t off = row*128 + (ks*16 + ((ln >> 3) & 1)*8)*2;
                off ^= (off >> 3) & 0x70;
                uint32_t r0, r1, r2, r3;
                ldsm4(r0, r1, r2, r3, bhB + off);
                bfh[2*p][0] = r0; bfh[2*p][1] = r1; bfh[2*p+1][0] = r2; bfh[2*p+1][1] = r3;
            }
            #pragma unroll
            for (int mt = 0; mt < 2; mt++)
                #pragma unroll
                for (int nt = 0; nt < 8; nt++){
                    mma_h(acc[mt][nt], afh[mt], bfh[nt]);                  // Ah*Bh
                    if (NT == 2) mma_h(acc[mt][nt], afl[mt], bfh[nt]);     // Al*Bh
                }
        }
        __syncthreads();
        if (tid == 0 && kt + NSTG < KT){
            MBARRIER_EXPECT_TX(sb + 8*st, STG_B);
            uint32_t base = sb + CTRL + st*STG_B;
            TMA2D(base,          &tAh, (kt+NSTG)*64, bm*128, sb + 8*st);
            if (NT == 2) TMA2D(base + A_PL, &tAl, (kt+NSTG)*64, bm*128, sb + 8*st);
            TMA2D(base + B_OFF,  &tBh, (kt+NSTG)*64, bn*128, sb + 8*st);
        }
        if (++st == NSTG){ st = 0; ph ^= 1; }
    }

    // ---- epilogue ----
    const int orow = bm*128 + wm*32;
    const int ocol = bn*128 + wn*64;
    #pragma unroll
    for (int mt = 0; mt < 2; mt++)
        #pragma unroll
        for (int nt = 0; nt < 8; nt++){
            float* a = acc[mt][nt];
            int r0 = orow + mt*16 + (ln >> 2);
            int c0 = ocol + nt*8 + (ln & 3)*2;
            if (mode == 0){
                #pragma unroll
                for (int q = 0; q < 2; q++){
                    size_t o = (size_t)(r0 + q*8)*N + c0;
                    __half h0 = __float2half_rn(a[2*q]);
                    __half h1 = __float2half_rn(a[2*q+1]);
                    *(__half2*)(Ch + o) = __halves2half2(h0, h1);
                    *(__half2*)(Cl + o) = __halves2half2(
                        __float2half_rn(a[2*q]   - __half2float(h0)),
                        __float2half_rn(a[2*q+1] - __half2float(h1)));
                }
            } else if (mode == 1){
                int g = (c0 >> 9) & 3;
                float b0 = bias[c0], b1 = bias[c0+1];
                float v00 = gate_act(a[0] + b0, g), v01 = gate_act(a[1] + b1, g);
                float v10 = gate_act(a[2] + b0, g), v11 = gate_act(a[3] + b1, g);
                *(float2*)(Cf + (size_t)r0*N + c0)     = float2{v00, v01};
                *(float2*)(Cf + (size_t)(r0+8)*N + c0) = float2{v10, v11};
            } else {
                *(float2*)(Cf + (size_t)r0*N + c0)     = float2{a[0], a[1]};
                *(float2*)(Cf + (size_t)(r0+8)*N + c0) = float2{a[2], a[3]};
            }
        }
}

// ---------------- scan pass 1: per-chunk (A = prod f, B) — gates pre-activated ----------------
__global__ void scan_pass1(){
    int blk = blockIdx.x;
    int ch = blk / BH_, bh = blk % BH_;
    int b = bh / NH_, h = bh % NH_;
    int d = threadIdx.x;
    float A = 1.f, Bv = 0.f;
    for (int s = 0; s < CH_; s++){
        int tok = b*L_ + ch*CH_ + s;
        size_t base = (size_t)tok*GN_ + h*(4*HD_) + d;
        float ig = g_gates[base], f = g_gates[base + HD_], cd = g_gates[base + 3*HD_];
        Bv = f*Bv + ig*cd;
        A *= f;
    }
    g_scanA[ch*BHD_ + bh*HD_ + d] = A;
    g_scanB[ch*BHD_ + bh*HD_ + d] = Bv;
}

// ---------------- scan pass 2: sequential chunk composition ----------------
__global__ void scan_pass2(){
    int idx = blockIdx.x*blockDim.x + threadIdx.x;
    float c = 0.f;
    for (int ch = 0; ch < NCH_; ch++){
        g_carry[ch*BHD_ + idx] = c;
        c = g_scanA[ch*BHD_ + idx]*c + g_scanB[ch*BHD_ + idx];
    }
}

// ---------------- scan pass 3: replay + RMS norm + h (fp16 out) ----------------
__global__ void scan_pass3(const float* __restrict__ rms_w){
    __shared__ float red[16];
    __shared__ float s_norm;
    int blk = blockIdx.x;
    int ch = blk / BH_, bh = blk % BH_;
    int b = bh / NH_, h = bh % NH_;
    int d = threadIdx.x;
    int warp = d >> 5, lane = d & 31;
    float c = g_carry[ch*BHD_ + bh*HD_ + d];
    float w = rms_w[d];
    for (int s = 0; s < CH_; s++){
        int tok = b*L_ + ch*CH_ + s;
        size_t base = (size_t)tok*GN_ + h*(4*HD_) + d;
        float ig = g_gates[base],          f  = g_gates[base + HD_];
        float og = g_gates[base + 2*HD_],  cd = g_gates[base + 3*HD_];
        c = f*c + ig*cd;
        float sq = c*c;
        #pragma unroll
        for (int o = 16; o; o >>= 1) sq += __shfl_xor_sync(0xffffffffu, sq, o);
        if (!lane) red[warp] = sq;
        __syncthreads();
        if (warp == 0){
            float vv = (lane < 16) ? red[lane] : 0.f;
            #pragma unroll
            for (int o = 8; o; o >>= 1) vv += __shfl_xor_sync(0xffffffffu, vv, o);
            if (!lane) s_norm = rsqrtf(vv*(1.f/HD_) + EPS_);
        }
        __syncthreads();
        float cn = c * s_norm * w;
        float hv = og * tanhf(cn);
        g_hh[(size_t)tok*HID_ + h*HD_ + d] = __float2half_rn(hv);
    }
}

// ---------------- host side ----------------
typedef CUresult (*PFN_encode_t)(CUtensorMap*, CUtensorMapDataType, cuuint32_t, void*,
                                 const cuuint64_t*, const cuuint64_t*, const cuuint32_t*,
                                 const cuuint32_t*, CUtensorMapInterleave, CUtensorMapSwizzle,
                                 CUtensorMapL2promotion, CUtensorMapFloatOOBfill);

static void enc_map16(PFN_encode_t fn, CUtensorMap* m, void* gaddr, uint64_t rows){
    cuuint64_t dims[2]    = {KROW_, rows};
    cuuint64_t strides[1] = {KROW_ * 2};
    cuuint32_t box[2]     = {64u, 128u};
    cuuint32_t es[2]      = {1u, 1u};
    fn(m, CU_TENSOR_MAP_DATA_TYPE_FLOAT16, 2, gaddr, dims, strides, box, es,
       CU_TENSOR_MAP_INTERLEAVE_NONE, CU_TENSOR_MAP_SWIZZLE_128B,
       CU_TENSOR_MAP_L2_PROMOTION_L2_128B, CU_TENSOR_MAP_FLOAT_OOB_FILL_NONE);
}

extern "C" void kernel_launch(void* const* d_in, const int* in_sizes, int n_in,
                              void* d_out, int out_size){
    const float* x      = (const float*)d_in[0];
    const float* W_in   = (const float*)d_in[1];
    const float* W_gate = (const float*)d_in[2];
    const float* b_gate = (const float*)d_in[3];
    const float* rms_w  = (const float*)d_in[4];
    const float* W_out  = (const float*)d_in[5];

    void *xh, *xl, *wih, *wgh, *woh, *xph, *xpl, *gts, *hh;
    cudaGetSymbolAddress(&xh,  g_xh);   cudaGetSymbolAddress(&xl,  g_xl);
    cudaGetSymbolAddress(&wih, g_Wih);  cudaGetSymbolAddress(&wgh, g_Wgh);
    cudaGetSymbolAddress(&woh, g_Woh);
    cudaGetSymbolAddress(&xph, g_xph);  cudaGetSymbolAddress(&xpl, g_xpl);
    cudaGetSymbolAddress(&gts, g_gates);
    cudaGetSymbolAddress(&hh,  g_hh);

    void* pfn = nullptr;
    cudaDriverEntryPointQueryResult qr;
    cudaGetDriverEntryPoint("cuTensorMapEncodeTiled", &pfn, cudaEnableDefault, &qr);
    PFN_encode_t enc = (PFN_encode_t)pfn;

    CUtensorMap mXh, mXl, mWih, mXph, mWgh, mHh, mWoh;
    enc_map16(enc, &mXh,  xh,  NTOK_);  enc_map16(enc, &mXl,  xl,  NTOK_);
    enc_map16(enc, &mWih, wih, HID_);
    enc_map16(enc, &mXph, xph, NTOK_);
    enc_map16(enc, &mWgh, wgh, GN_);
    enc_map16(enc, &mHh,  hh,  NTOK_);
    enc_map16(enc, &mWoh, woh, DIM_);

    const int SM2 = CTRL + 2*(3*A_PL);   // 2-term, 2-stage: 99328
    const int SM1 = CTRL + 3*(2*A_PL);   // 1-term, 3-stage: 99328
    cudaFuncSetAttribute(gemm_f16<2,2>, cudaFuncAttributeMaxDynamicSharedMemorySize, SM2);
    cudaFuncSetAttribute(gemm_f16<1,3>, cudaFuncAttributeMaxDynamicSharedMemorySize, SM1);

    int n4;
    n4 = NTOK_*DIM_/4; split16<<<(n4+255)/256, 256>>>(x,      (__half*)xh,  (__half*)xl, n4); // 0
    n4 = HID_*DIM_/4;  split16<<<(n4+255)/256, 256>>>(W_in,   (__half*)wih, nullptr, n4);     // 1
    n4 = GN_*HID_/4;   split16<<<(n4+255)/256, 256>>>(W_gate, (__half*)wgh, nullptr, n4);     // 2

    // 3: G1: xp = x @ W_in^T -> fp16 hi/lo  (2-term exact A, 2-stage; profiled slot)
    gemm_f16<2,2><<<dim3(HID_/128, NTOK_/128), 256, SM2>>>(
        mXh, mXl, mWih, nullptr, nullptr,
        (__half*)xph, (__half*)xpl, HID_, KROW_/64, 0);

    n4 = DIM_*HID_/4;  split16<<<(n4+255)/256, 256>>>(W_out, (__half*)woh, nullptr, n4);      // 4

    // G2: gates = act(xp_hi @ W_gate^T + b_gate) -> fp32  (1-term, 3-stage)
    gemm_f16<1,3><<<dim3(GN_/128, NTOK_/128), 256, SM1>>>(
        mXph, mXph, mWgh, b_gate, (float*)gts,
        nullptr, nullptr, GN_, KROW_/64, 1);

    // chunked parallel scan
    scan_pass1<<<NCH_*BH_, HD_>>>();
    scan_pass2<<<BHD_/256, 256>>>();
    scan_pass3<<<NCH_*BH_, HD_>>>(rms_w);

    // G3: out = h @ W_out^T -> fp32 to d_out  (1-term, 3-stage)
    gemm_f16<1,3><<<dim3(DIM_/128, NTOK_/128), 256, SM1>>>(
        mHh, mHh, mWoh, nullptr, (float*)d_out,
        nullptr, nullptr, DIM_, KROW_/64, 2);
}

// round 13
// speedup vs baseline: 8.3257x; 1.1253x over previous
#include <cuda.h>
#include <cuda_runtime.h>
#include <cuda_fp16.h>
#include <stdint.h>

#define DIM_  2048
#define HID_  2048
#define NH_   4
#define HD_   512
#define B_    4
#define L_    2048
#define NTOK_ 8192
#define GN_   8192
#define EPS_  1e-6f
#define CH_   64
#define NCH_  32
#define BH_   16
#define BHD_  (BH_*HD_)
#define KROW_ 2048

// ---------------- device scratch ----------------
__device__ __align__(1024) __half g_xh[(size_t)NTOK_*DIM_];
__device__ __align__(1024) __half g_Wih[(size_t)HID_*DIM_];
__device__ __align__(1024) __half g_Wgh[(size_t)GN_*HID_];
__device__ __align__(1024) __half g_Woh[(size_t)DIM_*HID_];
__device__ __align__(1024) __half g_xph[(size_t)NTOK_*HID_];
__device__ __align__(1024) float  g_gates[(size_t)NTOK_*GN_];   // activated gates
__device__ __align__(1024) __half g_hh[(size_t)NTOK_*HID_];
__device__ float g_scanA[NCH_*BHD_], g_scanB[NCH_*BHD_], g_carry[NCH_*BHD_];

// ---------------- helpers ----------------
__device__ __forceinline__ uint32_t smem_u32(const void* p){
    uint32_t a;
    asm("{ .reg .u64 t; cvta.to.shared.u64 t, %1; cvt.u32.u64 %0, t; }" : "=r"(a) : "l"(p));
    return a;
}

#define MBARRIER_INIT(a, cnt) \
    asm volatile("mbarrier.init.shared.b64 [%0], %1;" :: "r"(a), "r"(cnt) : "memory")
#define MBARRIER_EXPECT_TX(a, tx) \
    asm volatile("mbarrier.arrive.expect_tx.shared.b64 _, [%0], %1;" :: "r"(a), "r"(tx) : "memory")

__device__ __forceinline__ void bar_wait(uint32_t mbar, uint32_t parity){
    asm volatile("{\n\t.reg .pred P;\n\t"
        "W_%=:\n\t"
        "mbarrier.try_wait.parity.shared.b64 P, [%0], %1;\n\t"
        "@!P bra W_%=;\n\t}"
        :: "r"(mbar), "r"(parity) : "memory");
}

#define TMA2D(dst, map, x, y, mbar) \
    asm volatile("cp.async.bulk.tensor.2d.shared::cta.global.tile.mbarrier::complete_tx::bytes " \
        "[%0], [%1, {%2, %3}], [%4];" \
        :: "r"(dst), "l"(map), "r"(x), "r"(y), "r"(mbar) : "memory")

__device__ __forceinline__ void ldsm4(uint32_t& r0, uint32_t& r1, uint32_t& r2, uint32_t& r3, uint32_t a){
    asm volatile("ldmatrix.sync.aligned.m8n8.x4.shared.b16 {%0,%1,%2,%3}, [%4];"
        : "=r"(r0), "=r"(r1), "=r"(r2), "=r"(r3) : "r"(a));
}
__device__ __forceinline__ void mma_h(float* d, const uint32_t* a, const uint32_t* b){
    asm volatile("mma.sync.aligned.m16n8k16.row.col.f32.f16.f16.f32 "
        "{%0,%1,%2,%3},{%4,%5,%6,%7},{%8,%9},{%0,%1,%2,%3};"
        : "+f"(d[0]), "+f"(d[1]), "+f"(d[2]), "+f"(d[3])
        : "r"(a[0]), "r"(a[1]), "r"(a[2]), "r"(a[3]), "r"(b[0]), "r"(b[1]));
}

// ---------------- convert fp32 -> fp16 ----------------
__global__ void to16(const float* __restrict__ src, __half* __restrict__ dst, int n4){
    int i = blockIdx.x*blockDim.x + threadIdx.x;
    if (i >= n4) return;
    float4 v = ((const float4*)src)[i];
    __half2* D = (__half2*)dst;
    D[2*i]   = __halves2half2(__float2half_rn(v.x), __float2half_rn(v.y));
    D[2*i+1] = __halves2half2(__float2half_rn(v.z), __float2half_rn(v.w));
}

// ---------------- TMA-fed fp16 HMMA GEMM: C[M,N] = A[M,K]*B[N,K]^T ----------------
// CTA tile 128x128, BK=64 fp16 (128B rows, SW128), 8 warps (32x64), occ 2,
// 3-stage TMA ring (prefetch distance 3 covers TMA round-trip at 1-term compute).
#define A_PL 16384
#define STG_B (2*A_PL)      // 32768: A + B
#define NSTG 3
#define CTRL 1024
#define GSMEM (CTRL + NSTG*STG_B)   // 99328

__device__ __forceinline__ float gate_act(float v, int g){
    if (g == 0) return __expf(v);
    if (g == 3) return tanhf(v);
    return 1.f/(1.f + __expf(-v));
}

__global__ void __launch_bounds__(256, 2) gemm_f16(
    const __grid_constant__ CUtensorMap tA, const __grid_constant__ CUtensorMap tB,
    const float* __restrict__ bias, float* __restrict__ Cf,
    __half* __restrict__ Ch,
    int N, int KT, int mode)   // mode 0: fp16 out; 1: bias+gate-activation fp32; 2: fp32
{
    extern __shared__ char smem[];
    uint32_t sb = smem_u32(smem);
    const int tid = threadIdx.x;
    const int bm = blockIdx.y, bn = blockIdx.x;

    if (tid == 0){
        #pragma unroll
        for (int s = 0; s < NSTG; s++) MBARRIER_INIT(sb + 8*s, 1);
    }
    __syncthreads();
    if (tid == 0){
        #pragma unroll
        for (int st = 0; st < NSTG; st++){
            MBARRIER_EXPECT_TX(sb + 8*st, STG_B);
            uint32_t base = sb + CTRL + st*STG_B;
            TMA2D(base,        &tA, st*64, bm*128, sb + 8*st);
            TMA2D(base + A_PL, &tB, st*64, bn*128, sb + 8*st);
        }
    }

    const int warp = tid >> 5, ln = tid & 31;
    const int wm = warp >> 1, wn = warp & 1;

    float acc[2][8][4];
    #pragma unroll
    for (int a = 0; a < 2; a++)
        #pragma unroll
        for (int b = 0; b < 8; b++)
            #pragma unroll
            for (int q = 0; q < 4; q++) acc[a][b][q] = 0.f;

    int st = 0, ph = 0;

    for (int kt = 0; kt < KT; kt++){
        bar_wait(sb + 8*st, ph);

        const uint32_t aB = sb + CTRL + st*STG_B;
        const uint32_t bB = aB + A_PL;

        #pragma unroll
        for (int ks = 0; ks < 4; ks++){
            uint32_t af[2][4];
            #pragma unroll
            for (int mt = 0; mt < 2; mt++){
                uint32_t row = wm*32 + mt*16 + ((ln >> 3) & 1)*8 + (ln & 7);
                uint32_t off = row*128 + (ks*16 + (ln >> 4)*8)*2;
                off ^= (off >> 3) & 0x70;
                ldsm4(af[mt][0], af[mt][1], af[mt][2], af[mt][3], aB + off);
            }
            uint32_t bf[8][2];
            #pragma unroll
            for (int p = 0; p < 4; p++){
                uint32_t row = wn*64 + p*16 + (ln >> 4)*8 + (ln & 7);
                uint32_t off = row*128 + (ks*16 + ((ln >> 3) & 1)*8)*2;
                off ^= (off >> 3) & 0x70;
                uint32_t r0, r1, r2, r3;
                ldsm4(r0, r1, r2, r3, bB + off);
                bf[2*p][0] = r0; bf[2*p][1] = r1; bf[2*p+1][0] = r2; bf[2*p+1][1] = r3;
            }
            #pragma unroll
            for (int mt = 0; mt < 2; mt++)
                #pragma unroll
                for (int nt = 0; nt < 8; nt++)
                    mma_h(acc[mt][nt], af[mt], bf[nt]);
        }
        __syncthreads();
        if (tid == 0 && kt + NSTG < KT){
            MBARRIER_EXPECT_TX(sb + 8*st, STG_B);
            uint32_t base = sb + CTRL + st*STG_B;
            TMA2D(base,        &tA, (kt+NSTG)*64, bm*128, sb + 8*st);
            TMA2D(base + A_PL, &tB, (kt+NSTG)*64, bn*128, sb + 8*st);
        }
        if (++st == NSTG){ st = 0; ph ^= 1; }
    }

    // ---- epilogue ----
    const int orow = bm*128 + wm*32;
    const int ocol = bn*128 + wn*64;
    #pragma unroll
    for (int mt = 0; mt < 2; mt++)
        #pragma unroll
        for (int nt = 0; nt < 8; nt++){
            float* a = acc[mt][nt];
            int r0 = orow + mt*16 + (ln >> 2);
            int c0 = ocol + nt*8 + (ln & 3)*2;
            if (mode == 0){
                #pragma unroll
                for (int q = 0; q < 2; q++){
                    size_t o = (size_t)(r0 + q*8)*N + c0;
                    *(__half2*)(Ch + o) = __halves2half2(
                        __float2half_rn(a[2*q]), __float2half_rn(a[2*q+1]));
                }
            } else if (mode == 1){
                int g = (c0 >> 9) & 3;
                float b0 = bias[c0], b1 = bias[c0+1];
                float v00 = gate_act(a[0] + b0, g), v01 = gate_act(a[1] + b1, g);
                float v10 = gate_act(a[2] + b0, g), v11 = gate_act(a[3] + b1, g);
                *(float2*)(Cf + (size_t)r0*N + c0)     = float2{v00, v01};
                *(float2*)(Cf + (size_t)(r0+8)*N + c0) = float2{v10, v11};
            } else {
                *(float2*)(Cf + (size_t)r0*N + c0)     = float2{a[0], a[1]};
                *(float2*)(Cf + (size_t)(r0+8)*N + c0) = float2{a[2], a[3]};
            }
        }
}

// ---------------- scan pass 1: per-chunk (A = prod f, B) — gates pre-activated ----------------
__global__ void scan_pass1(){
    int blk = blockIdx.x;
    int ch = blk / BH_, bh = blk % BH_;
    int b = bh / NH_, h = bh % NH_;
    int d = threadIdx.x;
    float A = 1.f, Bv = 0.f;
    for (int s = 0; s < CH_; s++){
        int tok = b*L_ + ch*CH_ + s;
        size_t base = (size_t)tok*GN_ + h*(4*HD_) + d;
        float ig = g_gates[base], f = g_gates[base + HD_], cd = g_gates[base + 3*HD_];
        Bv = f*Bv + ig*cd;
        A *= f;
    }
    g_scanA[ch*BHD_ + bh*HD_ + d] = A;
    g_scanB[ch*BHD_ + bh*HD_ + d] = Bv;
}

// ---------------- scan pass 2: sequential chunk composition ----------------
__global__ void scan_pass2(){
    int idx = blockIdx.x*blockDim.x + threadIdx.x;
    float c = 0.f;
    for (int ch = 0; ch < NCH_; ch++){
        g_carry[ch*BHD_ + idx] = c;
        c = g_scanA[ch*BHD_ + idx]*c + g_scanB[ch*BHD_ + idx];
    }
}

// ---------------- scan pass 3: replay + RMS norm + h (fp16 out) ----------------
__global__ void scan_pass3(const float* __restrict__ rms_w){
    __shared__ float red[16];
    __shared__ float s_norm;
    int blk = blockIdx.x;
    int ch = blk / BH_, bh = blk % BH_;
    int b = bh / NH_, h = bh % NH_;
    int d = threadIdx.x;
    int warp = d >> 5, lane = d & 31;
    float c = g_carry[ch*BHD_ + bh*HD_ + d];
    float w = rms_w[d];
    for (int s = 0; s < CH_; s++){
        int tok = b*L_ + ch*CH_ + s;
        size_t base = (size_t)tok*GN_ + h*(4*HD_) + d;
        float ig = g_gates[base],          f  = g_gates[base + HD_];
        float og = g_gates[base + 2*HD_],  cd = g_gates[base + 3*HD_];
        c = f*c + ig*cd;
        float sq = c*c;
        #pragma unroll
        for (int o = 16; o; o >>= 1) sq += __shfl_xor_sync(0xffffffffu, sq, o);
        if (!lane) red[warp] = sq;
        __syncthreads();
        if (warp == 0){
            float vv = (lane < 16) ? red[lane] : 0.f;
            #pragma unroll
            for (int o = 8; o; o >>= 1) vv += __shfl_xor_sync(0xffffffffu, vv, o);
            if (!lane) s_norm = rsqrtf(vv*(1.f/HD_) + EPS_);
        }
        __syncthreads();
        float cn = c * s_norm * w;
        float hv = og * tanhf(cn);
        g_hh[(size_t)tok*HID_ + h*HD_ + d] = __float2half_rn(hv);
    }
}

// ---------------- host side ----------------
typedef CUresult (*PFN_encode_t)(CUtensorMap*, CUtensorMapDataType, cuuint32_t, void*,
                                 const cuuint64_t*, const cuuint64_t*, const cuuint32_t*,
                                 const cuuint32_t*, CUtensorMapInterleave, CUtensorMapSwizzle,
                                 CUtensorMapL2promotion, CUtensorMapFloatOOBfill);

static void enc_map16(PFN_encode_t fn, CUtensorMap* m, void* gaddr, uint64_t rows){
    cuuint64_t dims[2]    = {KROW_, rows};
    cuuint64_t strides[1] = {KROW_ * 2};
    cuuint32_t box[2]     = {64u, 128u};
    cuuint32_t es[2]      = {1u, 1u};
    fn(m, CU_TENSOR_MAP_DATA_TYPE_FLOAT16, 2, gaddr, dims, strides, box, es,
       CU_TENSOR_MAP_INTERLEAVE_NONE, CU_TENSOR_MAP_SWIZZLE_128B,
       CU_TENSOR_MAP_L2_PROMOTION_L2_128B, CU_TENSOR_MAP_FLOAT_OOB_FILL_NONE);
}

extern "C" void kernel_launch(void* const* d_in, const int* in_sizes, int n_in,
                              void* d_out, int out_size){
    const float* x      = (const float*)d_in[0];
    const float* W_in   = (const float*)d_in[1];
    const float* W_gate = (const float*)d_in[2];
    const float* b_gate = (const float*)d_in[3];
    const float* rms_w  = (const float*)d_in[4];
    const float* W_out  = (const float*)d_in[5];

    void *xh, *wih, *wgh, *woh, *xph, *gts, *hh;
    cudaGetSymbolAddress(&xh,  g_xh);
    cudaGetSymbolAddress(&wih, g_Wih);  cudaGetSymbolAddress(&wgh, g_Wgh);
    cudaGetSymbolAddress(&woh, g_Woh);
    cudaGetSymbolAddress(&xph, g_xph);
    cudaGetSymbolAddress(&gts, g_gates);
    cudaGetSymbolAddress(&hh,  g_hh);

    void* pfn = nullptr;
    cudaDriverEntryPointQueryResult qr;
    cudaGetDriverEntryPoint("cuTensorMapEncodeTiled", &pfn, cudaEnableDefault, &qr);
    PFN_encode_t enc = (PFN_encode_t)pfn;

    CUtensorMap mX, mWi, mXp, mWg, mH, mWo;
    enc_map16(enc, &mX,  xh,  NTOK_);
    enc_map16(enc, &mWi, wih, HID_);
    enc_map16(enc, &mXp, xph, NTOK_);
    enc_map16(enc, &mWg, wgh, GN_);
    enc_map16(enc, &mH,  hh,  NTOK_);
    enc_map16(enc, &mWo, woh, DIM_);

    cudaFuncSetAttribute(gemm_f16, cudaFuncAttributeMaxDynamicSharedMemorySize, GSMEM);

    int n4;
    n4 = NTOK_*DIM_/4; to16<<<(n4+255)/256, 256>>>(x,      (__half*)xh,  n4);  // 0
    n4 = HID_*DIM_/4;  to16<<<(n4+255)/256, 256>>>(W_in,   (__half*)wih, n4);  // 1
    n4 = GN_*HID_/4;   to16<<<(n4+255)/256, 256>>>(W_gate, (__half*)wgh, n4);  // 2

    // 3: G1: xp = x @ W_in^T -> fp16   (1-term, 3-stage; profiled slot)
    gemm_f16<<<dim3(HID_/128, NTOK_/128), 256, GSMEM>>>(
        mX, mWi, nullptr, nullptr, (__half*)xph, HID_, KROW_/64, 0);

    n4 = DIM_*HID_/4;  to16<<<(n4+255)/256, 256>>>(W_out, (__half*)woh, n4);   // 4

    // G2: gates = act(xp @ W_gate^T + b_gate) -> fp32
    gemm_f16<<<dim3(GN_/128, NTOK_/128), 256, GSMEM>>>(
        mXp, mWg, b_gate, (float*)gts, nullptr, GN_, KROW_/64, 1);

    // chunked parallel scan
    scan_pass1<<<NCH_*BH_, HD_>>>();
    scan_pass2<<<BHD_/256, 256>>>();
    scan_pass3<<<NCH_*BH_, HD_>>>(rms_w);

    // G3: out = h @ W_out^T -> fp32 to d_out
    gemm_f16<<<dim3(DIM_/128, NTOK_/128), 256, GSMEM>>>(
        mH, mWo, nullptr, (float*)d_out, nullptr, DIM_, KROW_/64, 2);
}

// round 14
// speedup vs baseline: 8.4427x; 1.0141x over previous
#include <cuda.h>
#include <cuda_runtime.h>
#include <cuda_fp16.h>
#include <stdint.h>

#define DIM_  2048
#define HID_  2048
#define NH_   4
#define HD_   512
#define B_    4
#define L_    2048
#define NTOK_ 8192
#define GN_   8192
#define EPS_  1e-6f
#define CH_   64
#define NCH_  32
#define BH_   16
#define BHD_  (BH_*HD_)
#define KROW_ 2048

// ---------------- device scratch ----------------
__device__ __align__(1024) __half g_xh[(size_t)NTOK_*DIM_];
__device__ __align__(1024) __half g_Wih[(size_t)HID_*DIM_];
__device__ __align__(1024) __half g_Wgh[(size_t)GN_*HID_];
__device__ __align__(1024) __half g_Woh[(size_t)DIM_*HID_];
__device__ __align__(1024) __half g_xph[(size_t)NTOK_*HID_];
__device__ __align__(1024) __half g_gates[(size_t)NTOK_*GN_];   // activated gates, fp16
__device__ __align__(1024) __half g_hh[(size_t)NTOK_*HID_];
__device__ float g_scanA[NCH_*BHD_], g_scanB[NCH_*BHD_], g_carry[NCH_*BHD_];

// ---------------- helpers ----------------
__device__ __forceinline__ uint32_t smem_u32(const void* p){
    uint32_t a;
    asm("{ .reg .u64 t; cvta.to.shared.u64 t, %1; cvt.u32.u64 %0, t; }" : "=r"(a) : "l"(p));
    return a;
}

#define MBARRIER_INIT(a, cnt) \
    asm volatile("mbarrier.init.shared.b64 [%0], %1;" :: "r"(a), "r"(cnt) : "memory")
#define MBARRIER_EXPECT_TX(a, tx) \
    asm volatile("mbarrier.arrive.expect_tx.shared.b64 _, [%0], %1;" :: "r"(a), "r"(tx) : "memory")

__device__ __forceinline__ void bar_wait(uint32_t mbar, uint32_t parity){
    asm volatile("{\n\t.reg .pred P;\n\t"
        "W_%=:\n\t"
        "mbarrier.try_wait.parity.shared.b64 P, [%0], %1;\n\t"
        "@!P bra W_%=;\n\t}"
        :: "r"(mbar), "r"(parity) : "memory");
}

#define TMA2D(dst, map, x, y, mbar) \
    asm volatile("cp.async.bulk.tensor.2d.shared::cta.global.tile.mbarrier::complete_tx::bytes " \
        "[%0], [%1, {%2, %3}], [%4];" \
        :: "r"(dst), "l"(map), "r"(x), "r"(y), "r"(mbar) : "memory")

__device__ __forceinline__ void ldsm4(uint32_t& r0, uint32_t& r1, uint32_t& r2, uint32_t& r3, uint32_t a){
    asm volatile("ldmatrix.sync.aligned.m8n8.x4.shared.b16 {%0,%1,%2,%3}, [%4];"
        : "=r"(r0), "=r"(r1), "=r"(r2), "=r"(r3) : "r"(a));
}
__device__ __forceinline__ void mma_h(float* d, const uint32_t* a, const uint32_t* b){
    asm volatile("mma.sync.aligned.m16n8k16.row.col.f32.f16.f16.f32 "
        "{%0,%1,%2,%3},{%4,%5,%6,%7},{%8,%9},{%0,%1,%2,%3};"
        : "+f"(d[0]), "+f"(d[1]), "+f"(d[2]), "+f"(d[3])
        : "r"(a[0]), "r"(a[1]), "r"(a[2]), "r"(a[3]), "r"(b[0]), "r"(b[1]));
}

// ---------------- convert fp32 -> fp16 ----------------
__global__ void to16(const float* __restrict__ src, __half* __restrict__ dst, int n4){
    int i = blockIdx.x*blockDim.x + threadIdx.x;
    if (i >= n4) return;
    float4 v = ((const float4*)src)[i];
    __half2* D = (__half2*)dst;
    D[2*i]   = __halves2half2(__float2half_rn(v.x), __float2half_rn(v.y));
    D[2*i+1] = __halves2half2(__float2half_rn(v.z), __float2half_rn(v.w));
}

// ---------------- TMA-fed fp16 HMMA GEMM: C[M,N] = A[M,K]*B[N,K]^T ----------------
// CTA tile 128x128, BK=64 fp16 (128B rows, SW128), 8 warps (32x64), occ 2, 3-stage TMA ring.
#define A_PL 16384
#define STG_B (2*A_PL)      // 32768: A + B
#define NSTG 3
#define CTRL 1024
#define GSMEM (CTRL + NSTG*STG_B)   // 99328

__device__ __forceinline__ float gate_act(float v, int g){
    if (g == 0) return __expf(v);
    if (g == 3) return tanhf(v);
    return 1.f/(1.f + __expf(-v));
}

__global__ void __launch_bounds__(256, 2) gemm_f16(
    const __grid_constant__ CUtensorMap tA, const __grid_constant__ CUtensorMap tB,
    const float* __restrict__ bias, float* __restrict__ Cf,
    __half* __restrict__ Ch,
    int N, int KT, int mode)   // mode 0: fp16 out; 1: bias+gate-act fp16 out; 2: fp32 out
{
    extern __shared__ char smem[];
    uint32_t sb = smem_u32(smem);
    const int tid = threadIdx.x;
    const int bm = blockIdx.y, bn = blockIdx.x;

    if (tid == 0){
        #pragma unroll
        for (int s = 0; s < NSTG; s++) MBARRIER_INIT(sb + 8*s, 1);
    }
    __syncthreads();
    if (tid == 0){
        #pragma unroll
        for (int st = 0; st < NSTG; st++){
            MBARRIER_EXPECT_TX(sb + 8*st, STG_B);
            uint32_t base = sb + CTRL + st*STG_B;
            TMA2D(base,        &tA, st*64, bm*128, sb + 8*st);
            TMA2D(base + A_PL, &tB, st*64, bn*128, sb + 8*st);
        }
    }

    const int warp = tid >> 5, ln = tid & 31;
    const int wm = warp >> 1, wn = warp & 1;

    float acc[2][8][4];
    #pragma unroll
    for (int a = 0; a < 2; a++)
        #pragma unroll
        for (int b = 0; b < 8; b++)
            #pragma unroll
            for (int q = 0; q < 4; q++) acc[a][b][q] = 0.f;

    int st = 0, ph = 0;

    for (int kt = 0; kt < KT; kt++){
        bar_wait(sb + 8*st, ph);

        const uint32_t aB = sb + CTRL + st*STG_B;
        const uint32_t bB = aB + A_PL;

        #pragma unroll
        for (int ks = 0; ks < 4; ks++){
            uint32_t af[2][4];
            #pragma unroll
            for (int mt = 0; mt < 2; mt++){
                uint32_t row = wm*32 + mt*16 + ((ln >> 3) & 1)*8 + (ln & 7);
                uint32_t off = row*128 + (ks*16 + (ln >> 4)*8)*2;
                off ^= (off >> 3) & 0x70;
                ldsm4(af[mt][0], af[mt][1], af[mt][2], af[mt][3], aB + off);
            }
            uint32_t bf[8][2];
            #pragma unroll
            for (int p = 0; p < 4; p++){
                uint32_t row = wn*64 + p*16 + (ln >> 4)*8 + (ln & 7);
                uint32_t off = row*128 + (ks*16 + ((ln >> 3) & 1)*8)*2;
                off ^= (off >> 3) & 0x70;
                uint32_t r0, r1, r2, r3;
                ldsm4(r0, r1, r2, r3, bB + off);
                bf[2*p][0] = r0; bf[2*p][1] = r1; bf[2*p+1][0] = r2; bf[2*p+1][1] = r3;
            }
            #pragma unroll
            for (int mt = 0; mt < 2; mt++)
                #pragma unroll
                for (int nt = 0; nt < 8; nt++)
                    mma_h(acc[mt][nt], af[mt], bf[nt]);
        }
        __syncthreads();
        if (tid == 0 && kt + NSTG < KT){
            MBARRIER_EXPECT_TX(sb + 8*st, STG_B);
            uint32_t base = sb + CTRL + st*STG_B;
            TMA2D(base,        &tA, (kt+NSTG)*64, bm*128, sb + 8*st);
            TMA2D(base + A_PL, &tB, (kt+NSTG)*64, bn*128, sb + 8*st);
        }
        if (++st == NSTG){ st = 0; ph ^= 1; }
    }

    // ---- epilogue ----
    const int orow = bm*128 + wm*32;
    const int ocol = bn*128 + wn*64;
    #pragma unroll
    for (int mt = 0; mt < 2; mt++)
        #pragma unroll
        for (int nt = 0; nt < 8; nt++){
            float* a = acc[mt][nt];
            int r0 = orow + mt*16 + (ln >> 2);
            int c0 = ocol + nt*8 + (ln & 3)*2;
            if (mode == 0){
                #pragma unroll
                for (int q = 0; q < 2; q++){
                    size_t o = (size_t)(r0 + q*8)*N + c0;
                    *(__half2*)(Ch + o) = __halves2half2(
                        __float2half_rn(a[2*q]), __float2half_rn(a[2*q+1]));
                }
            } else if (mode == 1){
                int g = (c0 >> 9) & 3;
                float b0 = bias[c0], b1 = bias[c0+1];
                float v00 = gate_act(a[0] + b0, g), v01 = gate_act(a[1] + b1, g);
                float v10 = gate_act(a[2] + b0, g), v11 = gate_act(a[3] + b1, g);
                *(__half2*)(Ch + (size_t)r0*N + c0) =
                    __halves2half2(__float2half_rn(v00), __float2half_rn(v01));
                *(__half2*)(Ch + (size_t)(r0+8)*N + c0) =
                    __halves2half2(__float2half_rn(v10), __float2half_rn(v11));
            } else {
                *(float2*)(Cf + (size_t)r0*N + c0)     = float2{a[0], a[1]};
                *(float2*)(Cf + (size_t)(r0+8)*N + c0) = float2{a[2], a[3]};
            }
        }
}

// ---------------- scan pass 1: per-chunk (A = prod f, B) — gates pre-activated fp16 ----------------
__global__ void scan_pass1(){
    int blk = blockIdx.x;
    int ch = blk / BH_, bh = blk % BH_;
    int b = bh / NH_, h = bh % NH_;
    int d = threadIdx.x;
    float A = 1.f, Bv = 0.f;
    for (int s = 0; s < CH_; s++){
        int tok = b*L_ + ch*CH_ + s;
        size_t base = (size_t)tok*GN_ + h*(4*HD_) + d;
        float ig = __half2float(g_gates[base]);
        float f  = __half2float(g_gates[base + HD_]);
        float cd = __half2float(g_gates[base + 3*HD_]);
        Bv = f*Bv + ig*cd;
        A *= f;
    }
    g_scanA[ch*BHD_ + bh*HD_ + d] = A;
    g_scanB[ch*BHD_ + bh*HD_ + d] = Bv;
}

// ---------------- scan pass 2: sequential chunk composition ----------------
__global__ void scan_pass2(){
    int idx = blockIdx.x*blockDim.x + threadIdx.x;
    float c = 0.f;
    for (int ch = 0; ch < NCH_; ch++){
        g_carry[ch*BHD_ + idx] = c;
        c = g_scanA[ch*BHD_ + idx]*c + g_scanB[ch*BHD_ + idx];
    }
}

// ---------------- scan pass 3: replay + RMS norm + h (fp16 out) ----------------
__global__ void scan_pass3(const float* __restrict__ rms_w){
    __shared__ float red[16];
    __shared__ float s_norm;
    int blk = blockIdx.x;
    int ch = blk / BH_, bh = blk % BH_;
    int b = bh / NH_, h = bh % NH_;
    int d = threadIdx.x;
    int warp = d >> 5, lane = d & 31;
    float c = g_carry[ch*BHD_ + bh*HD_ + d];
    float w = rms_w[d];
    for (int s = 0; s < CH_; s++){
        int tok = b*L_ + ch*CH_ + s;
        size_t base = (size_t)tok*GN_ + h*(4*HD_) + d;
        float ig = __half2float(g_gates[base]);
        float f  = __half2float(g_gates[base + HD_]);
        float og = __half2float(g_gates[base + 2*HD_]);
        float cd = __half2float(g_gates[base + 3*HD_]);
        c = f*c + ig*cd;
        float sq = c*c;
        #pragma unroll
        for (int o = 16; o; o >>= 1) sq += __shfl_xor_sync(0xffffffffu, sq, o);
        if (!lane) red[warp] = sq;
        __syncthreads();
        if (warp == 0){
            float vv = (lane < 16) ? red[lane] : 0.f;
            #pragma unroll
            for (int o = 8; o; o >>= 1) vv += __shfl_xor_sync(0xffffffffu, vv, o);
            if (!lane) s_norm = rsqrtf(vv*(1.f/HD_) + EPS_);
        }
        __syncthreads();
        float cn = c * s_norm * w;
        float hv = og * tanhf(cn);
        g_hh[(size_t)tok*HID_ + h*HD_ + d] = __float2half_rn(hv);
    }
}

// ---------------- host side ----------------
typedef CUresult (*PFN_encode_t)(CUtensorMap*, CUtensorMapDataType, cuuint32_t, void*,
                                 const cuuint64_t*, const cuuint64_t*, const cuuint32_t*,
                                 const cuuint32_t*, CUtensorMapInterleave, CUtensorMapSwizzle,
                                 CUtensorMapL2promotion, CUtensorMapFloatOOBfill);

static void enc_map16(PFN_encode_t fn, CUtensorMap* m, void* gaddr, uint64_t rows){
    cuuint64_t dims[2]    = {KROW_, rows};
    cuuint64_t strides[1] = {KROW_ * 2};
    cuuint32_t box[2]     = {64u, 128u};
    cuuint32_t es[2]      = {1u, 1u};
    fn(m, CU_TENSOR_MAP_DATA_TYPE_FLOAT16, 2, gaddr, dims, strides, box, es,
       CU_TENSOR_MAP_INTERLEAVE_NONE, CU_TENSOR_MAP_SWIZZLE_128B,
       CU_TENSOR_MAP_L2_PROMOTION_L2_128B, CU_TENSOR_MAP_FLOAT_OOB_FILL_NONE);
}

extern "C" void kernel_launch(void* const* d_in, const int* in_sizes, int n_in,
                              void* d_out, int out_size){
    const float* x      = (const float*)d_in[0];
    const float* W_in   = (const float*)d_in[1];
    const float* W_gate = (const float*)d_in[2];
    const float* b_gate = (const float*)d_in[3];
    const float* rms_w  = (const float*)d_in[4];
    const float* W_out  = (const float*)d_in[5];

    void *xh, *wih, *wgh, *woh, *xph, *gts, *hh;
    cudaGetSymbolAddress(&xh,  g_xh);
    cudaGetSymbolAddress(&wih, g_Wih);  cudaGetSymbolAddress(&wgh, g_Wgh);
    cudaGetSymbolAddress(&woh, g_Woh);
    cudaGetSymbolAddress(&xph, g_xph);
    cudaGetSymbolAddress(&gts, g_gates);
    cudaGetSymbolAddress(&hh,  g_hh);

    void* pfn = nullptr;
    cudaDriverEntryPointQueryResult qr;
    cudaGetDriverEntryPoint("cuTensorMapEncodeTiled", &pfn, cudaEnableDefault, &qr);
    PFN_encode_t enc = (PFN_encode_t)pfn;

    CUtensorMap mX, mWi, mXp, mWg, mH, mWo;
    enc_map16(enc, &mX,  xh,  NTOK_);
    enc_map16(enc, &mWi, wih, HID_);
    enc_map16(enc, &mXp, xph, NTOK_);
    enc_map16(enc, &mWg, wgh, GN_);
    enc_map16(enc, &mH,  hh,  NTOK_);
    enc_map16(enc, &mWo, woh, DIM_);

    cudaFuncSetAttribute(gemm_f16, cudaFuncAttributeMaxDynamicSharedMemorySize, GSMEM);

    int n4;
    n4 = NTOK_*DIM_/4; to16<<<(n4+255)/256, 256>>>(x,      (__half*)xh,  n4);  // 0
    n4 = HID_*DIM_/4;  to16<<<(n4+255)/256, 256>>>(W_in,   (__half*)wih, n4);  // 1
    n4 = GN_*HID_/4;   to16<<<(n4+255)/256, 256>>>(W_gate, (__half*)wgh, n4);  // 2

    // 3: G1: xp = x @ W_in^T -> fp16   (profiled slot)
    gemm_f16<<<dim3(HID_/128, NTOK_/128), 256, GSMEM>>>(
        mX, mWi, nullptr, nullptr, (__half*)xph, HID_, KROW_/64, 0);

    n4 = DIM_*HID_/4;  to16<<<(n4+255)/256, 256>>>(W_out, (__half*)woh, n4);   // 4

    // G2: gates = act(xp @ W_gate^T + b_gate) -> fp16
    gemm_f16<<<dim3(GN_/128, NTOK_/128), 256, GSMEM>>>(
        mXp, mWg, b_gate, nullptr, (__half*)gts, GN_, KROW_/64, 1);

    // chunked parallel scan
    scan_pass1<<<NCH_*BH_, HD_>>>();
    scan_pass2<<<BHD_/256, 256>>>();
    scan_pass3<<<NCH_*BH_, HD_>>>(rms_w);

    // G3: out = h @ W_out^T -> fp32 to d_out
    gemm_f16<<<dim3(DIM_/128, NTOK_/128), 256, GSMEM>>>(
        mH, mWo, nullptr, (float*)d_out, nullptr, DIM_, KROW_/64, 2);
}